// round 4
// baseline (speedup 1.0000x reference)
#include <cuda_runtime.h>
#include <math.h>

// Problem constants
#define BB 4
#define SSEQ 4096
#define HH 8
#define DI 128
#define DOUT 128
#define HD 1024            // HH*DI
#define NTOK (BB*SSEQ)     // 16384
#define CH 256             // cumsum/scan chunk length
#define NCH 16             // SSEQ / CH
#define LANES (BB*HH*DI)   // 4096

// ---------------- scratch (static device globals; no allocations) -------------
__device__ float g_csum[NTOK * HD];          // exclusive cumsum, later normalized
__device__ float g_h3[NTOK * HH * 384];      // h3 raw; reused as og raw
__device__ float g_fg[NTOK * HD];            // forget gate (sigmoid)
__device__ float g_igh[NTOK * HD];           // sigmoid(i)*relu(h)
__device__ float g_cell[NTOK * HD];          // scan output
__device__ float g_ctot[LANES * NCH];        // cumsum chunk totals
__device__ float g_coff[LANES * NCH];        // cumsum chunk offsets
__device__ float g_aggF[LANES * NCH];        // scan chunk aggregate F
__device__ float g_aggI[LANES * NCH];        // scan chunk aggregate I
__device__ float g_carry[LANES * NCH];       // scan chunk incoming carry

__device__ __forceinline__ float sigmoidf_(float x) {
    return 1.0f / (1.0f + expf(-x));
}

// block-wide sum reduction (blockDim.x == 256), result broadcast to all threads
__device__ __forceinline__ float blockSum256(float v, float* red) {
    int tid = threadIdx.x;
    #pragma unroll
    for (int o = 16; o; o >>= 1) v += __shfl_xor_sync(0xffffffffu, v, o);
    if ((tid & 31) == 0) red[tid >> 5] = v;
    __syncthreads();
    if (tid < 32) {
        float x = (tid < 8) ? red[tid] : 0.0f;
        #pragma unroll
        for (int o = 4; o; o >>= 1) x += __shfl_xor_sync(0xffffffffu, x, o);
        if (tid == 0) red[0] = x;
    }
    __syncthreads();
    float r = red[0];
    __syncthreads();
    return r;
}

// ---------------- K1: per-chunk exclusive cumsum ------------------------------
__global__ void k_cumsum(const float* __restrict__ hi) {
    int part  = blockIdx.x & 3;
    int chunk = (blockIdx.x >> 2) & 15;
    int b     = blockIdx.x >> 6;
    int hd    = part * 256 + threadIdx.x;
    int base  = (b * SSEQ + chunk * CH) * HD + hd;
    float run = 0.0f;
    #pragma unroll 8
    for (int i = 0; i < CH; i++) {
        int idx = base + i * HD;
        float v = hi[idx];
        g_csum[idx] = run;
        run += v;
    }
    g_ctot[(b * HD + hd) * NCH + chunk] = run;
}

// ---------------- K2: scan chunk totals -> offsets ----------------------------
__global__ void k_scanoff() {
    int lane = blockIdx.x * 256 + threadIdx.x;  // 0..4095
    float run = 0.0f;
    #pragma unroll
    for (int c = 0; c < NCH; c++) {
        float t = g_ctot[lane * NCH + c];
        g_coff[lane * NCH + c] = run;
        run += t;
    }
}

// ---------------- K3: csum LayerNorm over (H,DI)=1024 per token ---------------
__global__ __launch_bounds__(256) void k_csum_ln(const float* __restrict__ gcs,
                                                 const float* __restrict__ bcs) {
    __shared__ float red[32];
    int t = blockIdx.x;          // token
    int b = t >> 12;
    int s = t & (SSEQ - 1);
    int chunk = s >> 8;
    int tid = threadIdx.x;
    float v[4];
    #pragma unroll
    for (int j = 0; j < 4; j++) {
        int hd = tid + j * 256;
        v[j] = g_csum[t * HD + hd] + g_coff[(b * HD + hd) * NCH + chunk];
    }
    float s1 = v[0] + v[1] + v[2] + v[3];
    s1 = blockSum256(s1, red);
    float mu = s1 * (1.0f / 1024.0f);
    float q = 0.0f;
    #pragma unroll
    for (int j = 0; j < 4; j++) { float d = v[j] - mu; q += d * d; }
    q = blockSum256(q, red);
    float rs = rsqrtf(q * (1.0f / 1024.0f) + 1e-6f);
    #pragma unroll
    for (int j = 0; j < 4; j++) {
        int hd = tid + j * 256;
        g_csum[t * HD + hd] = (v[j] - mu) * rs * gcs[hd] + bcs[hd];
    }
}

// ---------------- K4: GEMM1  h3 = [hi, csum_n] @ W_hid + b_hid ----------------
// per head: M=16384 N=384 K=256.  BM=64 BN=128 KC=32, 128 thr, 8x8 regs/thr
__global__ __launch_bounds__(128) void k_gemm1(const float* __restrict__ hi,
                                               const float* __restrict__ W,
                                               const float* __restrict__ bias) {
    int ntile = blockIdx.x;   // 0..2
    int mtile = blockIdx.y;   // 0..255
    int head  = blockIdx.z;   // 0..7
    int tok0 = mtile * 64;
    int n0 = ntile * 128;
    __shared__ float As[64][36];
    __shared__ float Bs[32][128];
    int tid = threadIdx.x;
    int mg = tid >> 4;   // 0..7
    int ng = tid & 15;   // 0..15
    float acc[8][8];
    #pragma unroll
    for (int i = 0; i < 8; i++)
        #pragma unroll
        for (int j = 0; j < 8; j++) acc[i][j] = 0.0f;

    for (int kc = 0; kc < 256; kc += 32) {
        const float* Asrc = (kc < 128) ? hi : g_csum;
        int kk0 = kc & 127;
        #pragma unroll
        for (int l = 0; l < 4; l++) {
            int id = tid + l * 128;
            int row = id >> 3;
            int c4 = id & 7;
            float4 vv = *(const float4*)(Asrc + ((tok0 + row) * HH + head) * DI + kk0 + c4 * 4);
            *(float4*)&As[row][c4 * 4] = vv;
        }
        #pragma unroll
        for (int l = 0; l < 8; l++) {
            int id = tid + l * 128;
            int r = id >> 5;
            int c4 = id & 31;
            float4 vv = *(const float4*)(W + (head * 256 + kc + r) * 384 + n0 + c4 * 4);
            *(float4*)&Bs[r][c4 * 4] = vv;
        }
        __syncthreads();
        #pragma unroll 4
        for (int k = 0; k < 32; k++) {
            float a[8], bb[8];
            #pragma unroll
            for (int i = 0; i < 8; i++) a[i] = As[mg * 8 + i][k];
            float4 b0 = *(const float4*)&Bs[k][ng * 8];
            float4 b1 = *(const float4*)&Bs[k][ng * 8 + 4];
            bb[0] = b0.x; bb[1] = b0.y; bb[2] = b0.z; bb[3] = b0.w;
            bb[4] = b1.x; bb[5] = b1.y; bb[6] = b1.z; bb[7] = b1.w;
            #pragma unroll
            for (int i = 0; i < 8; i++)
                #pragma unroll
                for (int j = 0; j < 8; j++)
                    acc[i][j] = fmaf(a[i], bb[j], acc[i][j]);
        }
        __syncthreads();
    }
    #pragma unroll
    for (int i = 0; i < 8; i++) {
        int tok = tok0 + mg * 8 + i;
        int obase = (tok * HH + head) * 384 + n0 + ng * 8;
        #pragma unroll
        for (int j = 0; j < 8; j++)
            g_h3[obase + j] = acc[i][j] + bias[head * 384 + n0 + ng * 8 + j];
    }
}

// ---------------- K5: LN over (H,3,DO)=3072 per token + gates -----------------
__global__ __launch_bounds__(256) void k_ln_gates(const float* __restrict__ gh,
                                                  const float* __restrict__ bh) {
    __shared__ float red[32];
    __shared__ float sm[3072];
    int t = blockIdx.x;
    int tid = threadIdx.x;
    float v[12];
    #pragma unroll
    for (int j = 0; j < 12; j++) v[j] = g_h3[t * 3072 + tid + j * 256];
    float s1 = 0.0f;
    #pragma unroll
    for (int j = 0; j < 12; j++) s1 += v[j];
    s1 = blockSum256(s1, red);
    float mu = s1 * (1.0f / 3072.0f);
    float q = 0.0f;
    #pragma unroll
    for (int j = 0; j < 12; j++) { float d = v[j] - mu; q += d * d; }
    q = blockSum256(q, red);
    float rs = rsqrtf(q * (1.0f / 3072.0f) + 1e-6f);
    #pragma unroll
    for (int j = 0; j < 12; j++) {
        int e = tid + j * 256;
        sm[e] = (v[j] - mu) * rs * gh[e] + bh[e];
    }
    __syncthreads();
    #pragma unroll
    for (int j = 0; j < 4; j++) {
        int idx = tid + j * 256;          // n*128 + d
        int n = idx >> 7;
        int d = idx & 127;
        float ig = sm[n * 384 + d];
        float fg = sm[n * 384 + 128 + d];
        float hv = sm[n * 384 + 256 + d];
        g_fg[t * HD + idx]  = sigmoidf_(fg);
        g_igh[t * HD + idx] = sigmoidf_(ig) * fmaxf(hv, 0.0f);
    }
}

// ---------------- K6a: scan chunk aggregates (F, I) ---------------------------
__global__ void k_scan_agg() {
    int gid = blockIdx.x * 256 + threadIdx.x;   // chunk*4096 + lane
    int lane = gid & 4095;
    int chunk = gid >> 12;
    int off = lane & 1023;
    int b = lane >> 10;
    int base = (b * SSEQ + chunk * CH) * HD + off;
    float F = 1.0f, I = 0.0f;
    #pragma unroll 4
    for (int i = 0; i < CH; i++) {
        int idx = base + i * HD;
        float f = g_fg[idx];
        I = f * I + g_igh[idx];
        F *= f;
    }
    g_aggF[gid] = F;
    g_aggI[gid] = I;
}

// ---------------- K6b: scan carries across chunks -----------------------------
__global__ void k_scan_carry(const float* __restrict__ init_cx) {
    int lane = blockIdx.x * 256 + threadIdx.x;  // 0..4095
    float c = init_cx[lane & 1023];
    #pragma unroll
    for (int chunk = 0; chunk < NCH; chunk++) {
        g_carry[chunk * 4096 + lane] = c;
        c = g_aggF[chunk * 4096 + lane] * c + g_aggI[chunk * 4096 + lane];
    }
}

// ---------------- K6c: apply scan, write cell ---------------------------------
__global__ void k_scan_apply() {
    int gid = blockIdx.x * 256 + threadIdx.x;
    int lane = gid & 4095;
    int chunk = gid >> 12;
    int off = lane & 1023;
    int b = lane >> 10;
    int base = (b * SSEQ + chunk * CH) * HD + off;
    float c = g_carry[gid];
    #pragma unroll 4
    for (int i = 0; i < CH; i++) {
        int idx = base + i * HD;
        c = g_fg[idx] * c + g_igh[idx];
        g_cell[idx] = c;
    }
}

// ---------------- K7: GEMM2  og = [hi, cell] @ W_og + b_og --------------------
// per head: M=16384 N=128 K=256
__global__ __launch_bounds__(128) void k_gemm2(const float* __restrict__ hi,
                                               const float* __restrict__ W,
                                               const float* __restrict__ bias) {
    int mtile = blockIdx.x;   // 0..255
    int head  = blockIdx.y;   // 0..7
    int tok0 = mtile * 64;
    __shared__ float As[64][36];
    __shared__ float Bs[32][128];
    int tid = threadIdx.x;
    int mg = tid >> 4;
    int ng = tid & 15;
    float acc[8][8];
    #pragma unroll
    for (int i = 0; i < 8; i++)
        #pragma unroll
        for (int j = 0; j < 8; j++) acc[i][j] = 0.0f;

    for (int kc = 0; kc < 256; kc += 32) {
        const float* Asrc = (kc < 128) ? hi : g_cell;
        int kk0 = kc & 127;
        #pragma unroll
        for (int l = 0; l < 4; l++) {
            int id = tid + l * 128;
            int row = id >> 3;
            int c4 = id & 7;
            float4 vv = *(const float4*)(Asrc + ((tok0 + row) * HH + head) * DI + kk0 + c4 * 4);
            *(float4*)&As[row][c4 * 4] = vv;
        }
        #pragma unroll
        for (int l = 0; l < 8; l++) {
            int id = tid + l * 128;
            int r = id >> 5;
            int c4 = id & 31;
            float4 vv = *(const float4*)(W + (head * 256 + kc + r) * 128 + c4 * 4);
            *(float4*)&Bs[r][c4 * 4] = vv;
        }
        __syncthreads();
        #pragma unroll 4
        for (int k = 0; k < 32; k++) {
            float a[8], bb[8];
            #pragma unroll
            for (int i = 0; i < 8; i++) a[i] = As[mg * 8 + i][k];
            float4 b0 = *(const float4*)&Bs[k][ng * 8];
            float4 b1 = *(const float4*)&Bs[k][ng * 8 + 4];
            bb[0] = b0.x; bb[1] = b0.y; bb[2] = b0.z; bb[3] = b0.w;
            bb[4] = b1.x; bb[5] = b1.y; bb[6] = b1.z; bb[7] = b1.w;
            #pragma unroll
            for (int i = 0; i < 8; i++)
                #pragma unroll
                for (int j = 0; j < 8; j++)
                    acc[i][j] = fmaf(a[i], bb[j], acc[i][j]);
        }
        __syncthreads();
    }
    #pragma unroll
    for (int i = 0; i < 8; i++) {
        int tok = tok0 + mg * 8 + i;
        int obase = (tok * HH + head) * 128 + ng * 8;   // og raw reuses g_h3
        #pragma unroll
        for (int j = 0; j < 8; j++)
            g_h3[obase + j] = acc[i][j] + bias[head * 128 + ng * 8 + j];
    }
}

// ---------------- K8: final LN over (H,DO)=1024 + sigmoid * cell --------------
__global__ __launch_bounds__(256) void k_final(const float* __restrict__ gog,
                                               const float* __restrict__ bog,
                                               float* __restrict__ out) {
    __shared__ float red[32];
    int t = blockIdx.x;
    int tid = threadIdx.x;
    float v[4];
    #pragma unroll
    for (int j = 0; j < 4; j++) v[j] = g_h3[t * HD + tid + j * 256];
    float s1 = v[0] + v[1] + v[2] + v[3];
    s1 = blockSum256(s1, red);
    float mu = s1 * (1.0f / 1024.0f);
    float q = 0.0f;
    #pragma unroll
    for (int j = 0; j < 4; j++) { float d = v[j] - mu; q += d * d; }
    q = blockSum256(q, red);
    float rs = rsqrtf(q * (1.0f / 1024.0f) + 1e-6f);
    #pragma unroll
    for (int j = 0; j < 4; j++) {
        int idx = tid + j * 256;
        float og = (v[j] - mu) * rs * gog[idx] + bog[idx];
        out[t * HD + idx] = sigmoidf_(og) * g_cell[t * HD + idx];
    }
}

// ------------------------------------------------------------------------------
extern "C" void kernel_launch(void* const* d_in, const int* in_sizes, int n_in,
                              void* d_out, int out_size) {
    const float* hi        = (const float*)d_in[0];
    const float* W_hid     = (const float*)d_in[1];
    const float* b_hid     = (const float*)d_in[2];
    const float* gcsum     = (const float*)d_in[3];
    const float* bcsum     = (const float*)d_in[4];
    const float* g_hid     = (const float*)d_in[5];
    const float* beta_hid  = (const float*)d_in[6];
    const float* W_og      = (const float*)d_in[7];
    const float* b_og      = (const float*)d_in[8];
    const float* g_og      = (const float*)d_in[9];
    const float* beta_og   = (const float*)d_in[10];
    const float* init_cx   = (const float*)d_in[11];
    float* out = (float*)d_out;

    k_cumsum<<<256, 256>>>(hi);
    k_scanoff<<<16, 256>>>();
    k_csum_ln<<<NTOK, 256>>>(gcsum, bcsum);
    k_gemm1<<<dim3(3, 256, 8), 128>>>(hi, W_hid, b_hid);
    k_ln_gates<<<NTOK, 256>>>(g_hid, beta_hid);
    k_scan_agg<<<256, 256>>>();
    k_scan_carry<<<16, 256>>>(init_cx);
    k_scan_apply<<<256, 256>>>();
    k_gemm2<<<dim3(256, 8), 128>>>(hi, W_og, b_og);
    k_final<<<NTOK, 256>>>(g_og, beta_og, out);
}

// round 7
// speedup vs baseline: 1.7292x; 1.7292x over previous
#include <cuda_runtime.h>
#include <cuda_bf16.h>
#include <cstdint>
#include <math.h>

// Problem constants
#define BB 4
#define SSEQ 4096
#define HH 8
#define DI 128
#define DOUT 128
#define HD 1024            // HH*DI
#define NTOK (BB*SSEQ)     // 16384
#define CH 256             // cumsum/scan chunk length
#define NCH 16             // SSEQ / CH
#define LANES (BB*HH*DI)   // 4096

// ---------------- scratch (static device globals; no allocations) -------------
__device__ float g_csum[NTOK * HD];          // exclusive cumsum, later normalized
__device__ float g_h3[NTOK * HH * 384];      // h3 raw; reused as og raw
__device__ float g_fg[NTOK * HD];            // forget gate (sigmoid)
__device__ float g_igh[NTOK * HD];           // sigmoid(i)*relu(h)
__device__ float g_cell[NTOK * HD];          // scan output
__device__ float g_ctot[LANES * NCH];
__device__ float g_coff[LANES * NCH];
__device__ float g_aggF[LANES * NCH];
__device__ float g_aggI[LANES * NCH];
__device__ float g_carry[LANES * NCH];

// bf16 hi/lo split weights, K-major ([head][n][k])
__device__ __nv_bfloat16 g_Wh_hi[8 * 384 * 256];
__device__ __nv_bfloat16 g_Wh_lo[8 * 384 * 256];
__device__ __nv_bfloat16 g_Wo_hi[8 * 128 * 256];
__device__ __nv_bfloat16 g_Wo_lo[8 * 128 * 256];

__device__ __forceinline__ float sigmoidf_(float x) {
    return 1.0f / (1.0f + expf(-x));
}

// ======================= mma.sync / ldmatrix helpers ==========================
__device__ __forceinline__ uint32_t s2u(const void* p) {
    uint32_t a;
    asm("{ .reg .u64 t; cvta.to.shared.u64 t, %1; cvt.u32.u64 %0, t; }" : "=r"(a) : "l"(p));
    return a;
}
__device__ __forceinline__ void ldsm4(uint32_t r[4], uint32_t addr) {
    asm volatile("ldmatrix.sync.aligned.m8n8.x4.shared.b16 {%0,%1,%2,%3}, [%4];"
                 : "=r"(r[0]), "=r"(r[1]), "=r"(r[2]), "=r"(r[3]) : "r"(addr));
}
__device__ __forceinline__ void mma16816(float* c, const uint32_t* a, const uint32_t* b) {
    asm volatile(
        "mma.sync.aligned.m16n8k16.row.col.f32.bf16.bf16.f32 "
        "{%0,%1,%2,%3}, {%4,%5,%6,%7}, {%8,%9}, {%0,%1,%2,%3};"
        : "+f"(c[0]), "+f"(c[1]), "+f"(c[2]), "+f"(c[3])
        : "r"(a[0]), "r"(a[1]), "r"(a[2]), "r"(a[3]), "r"(b[0]), "r"(b[1]));
}

// block-wide sum reduction (blockDim.x == 256), result broadcast
__device__ __forceinline__ float blockSum256(float v, float* red) {
    int tid = threadIdx.x;
    #pragma unroll
    for (int o = 16; o; o >>= 1) v += __shfl_xor_sync(0xffffffffu, v, o);
    if ((tid & 31) == 0) red[tid >> 5] = v;
    __syncthreads();
    if (tid < 32) {
        float x = (tid < 8) ? red[tid] : 0.0f;
        #pragma unroll
        for (int o = 4; o; o >>= 1) x += __shfl_xor_sync(0xffffffffu, x, o);
        if (tid == 0) red[0] = x;
    }
    __syncthreads();
    float r = red[0];
    __syncthreads();
    return r;
}

// ---------------- K1: per-chunk exclusive cumsum ------------------------------
__global__ void k_cumsum(const float* __restrict__ hi) {
    int part  = blockIdx.x & 3;
    int chunk = (blockIdx.x >> 2) & 15;
    int b     = blockIdx.x >> 6;
    int hd    = part * 256 + threadIdx.x;
    int base  = (b * SSEQ + chunk * CH) * HD + hd;
    float run = 0.0f;
    #pragma unroll 8
    for (int i = 0; i < CH; i++) {
        int idx = base + i * HD;
        float v = hi[idx];
        g_csum[idx] = run;
        run += v;
    }
    g_ctot[(b * HD + hd) * NCH + chunk] = run;
}

// ---------------- K2: scan chunk totals -> offsets ----------------------------
__global__ void k_scanoff() {
    int lane = blockIdx.x * 256 + threadIdx.x;
    float run = 0.0f;
    #pragma unroll
    for (int c = 0; c < NCH; c++) {
        float t = g_ctot[lane * NCH + c];
        g_coff[lane * NCH + c] = run;
        run += t;
    }
}

// ---------------- K3: csum LayerNorm over (H,DI)=1024 per token ---------------
__global__ __launch_bounds__(256) void k_csum_ln(const float* __restrict__ gcs,
                                                 const float* __restrict__ bcs) {
    __shared__ float red[32];
    int t = blockIdx.x;
    int b = t >> 12;
    int s = t & (SSEQ - 1);
    int chunk = s >> 8;
    int tid = threadIdx.x;
    float v[4];
    #pragma unroll
    for (int j = 0; j < 4; j++) {
        int hd = tid + j * 256;
        v[j] = g_csum[t * HD + hd] + g_coff[(b * HD + hd) * NCH + chunk];
    }
    float s1 = v[0] + v[1] + v[2] + v[3];
    s1 = blockSum256(s1, red);
    float mu = s1 * (1.0f / 1024.0f);
    float q = 0.0f;
    #pragma unroll
    for (int j = 0; j < 4; j++) { float d = v[j] - mu; q += d * d; }
    q = blockSum256(q, red);
    float rs = rsqrtf(q * (1.0f / 1024.0f) + 1e-6f);
    #pragma unroll
    for (int j = 0; j < 4; j++) {
        int hd = tid + j * 256;
        g_csum[t * HD + hd] = (v[j] - mu) * rs * gcs[hd] + bcs[hd];
    }
}

// ---------------- Weight prep: fp32 -> bf16 hi/lo, transpose to [h][n][k] -----
__global__ void k_prepW1(const float* __restrict__ W) {   // W_hid (8,256,384)
    int gid = blockIdx.x * 256 + threadIdx.x;             // h*256*384 + k*384 + n
    int n = gid % 384;
    int hk = gid / 384;
    int k = hk & 255;
    int h = hk >> 8;
    float v = W[gid];
    __nv_bfloat16 hh = __float2bfloat16_rn(v);
    __nv_bfloat16 ll = __float2bfloat16_rn(v - __bfloat162float(hh));
    int o = (h * 384 + n) * 256 + k;
    g_Wh_hi[o] = hh;
    g_Wh_lo[o] = ll;
}
__global__ void k_prepW2(const float* __restrict__ W) {   // W_og (8,256,128)
    int gid = blockIdx.x * 256 + threadIdx.x;             // h*32768 + k*128 + n
    int n = gid & 127;
    int k = (gid >> 7) & 255;
    int h = gid >> 15;
    float v = W[gid];
    __nv_bfloat16 hh = __float2bfloat16_rn(v);
    __nv_bfloat16 ll = __float2bfloat16_rn(v - __bfloat162float(hh));
    int o = (h * 128 + n) * 256 + k;
    g_Wo_hi[o] = hh;
    g_Wo_lo[o] = ll;
}

// ---------------- GEMM via mma.sync bf16 hi/lo emulation ----------------------
// CTA tile 128(M) x 128(N), one head. K=256 in 4 chunks of 64.
// 256 threads = 8 warps in 2(m) x 4(n); warp tile 64x32; mma m16n8k16.
// SMEM: padded bf16 tiles, row stride 72 elems (144 B) -> LDSM conflict-free.
#define TSTRIDE 72
#define TBYTES  (128 * TSTRIDE * 2)      // 18432 per tile
#define SM_AHI  0
#define SM_ALO  (TBYTES)
#define SM_BHI  (2 * TBYTES)
#define SM_BLO  (3 * TBYTES)
#define SM_GEMM (4 * TBYTES)             // 73728 bytes

__global__ __launch_bounds__(256, 2) void k_gemm_mma(
    const float* __restrict__ A1,        // K-half 0 source (heads_input)
    const float* __restrict__ A2,        // K-half 1 source (csum_n or cell)
    const __nv_bfloat16* __restrict__ Whi,
    const __nv_bfloat16* __restrict__ Wlo,
    const float* __restrict__ bias,
    float* __restrict__ out,
    int Nw)                              // 384 (gemm1) or 128 (gemm2)
{
    extern __shared__ char sm[];
    uint32_t sb = s2u(sm);
    int tid = threadIdx.x;
    int wid = tid >> 5, lid = tid & 31;
    int warp_m = wid >> 2, warp_n = wid & 3;
    int mtile = blockIdx.x, ntile = blockIdx.y, head = blockIdx.z;
    int tok0 = mtile * 128;
    int n0 = ntile * 128;

    float acc[4][4][4];
    #pragma unroll
    for (int i = 0; i < 4; i++)
        #pragma unroll
        for (int j = 0; j < 4; j++)
            #pragma unroll
            for (int e = 0; e < 4; e++) acc[i][j][e] = 0.0f;

    // ldmatrix lane address components
    int sub = lid >> 3, rin = lid & 7;

    for (int c = 0; c < 4; c++) {
        const float* Asrc = (c < 2) ? A1 : A2;
        int kb = (c & 1) * 64;
        // ---- A: fp32 -> bf16 hi/lo into padded SMEM --------------------------
        #pragma unroll
        for (int g = tid; g < 1024; g += 256) {
            int r = g >> 3, q = g & 7;
            const float* p = Asrc + ((long)(tok0 + r) * 8 + head) * 128 + kb + q * 8;
            float4 u0 = *(const float4*)p;
            float4 u1 = *(const float4*)(p + 4);
            float v[8] = {u0.x, u0.y, u0.z, u0.w, u1.x, u1.y, u1.z, u1.w};
            union { __nv_bfloat16 h[8]; uint4 u; } H, L;
            #pragma unroll
            for (int j = 0; j < 8; j++) {
                __nv_bfloat16 hh = __float2bfloat16_rn(v[j]);
                H.h[j] = hh;
                L.h[j] = __float2bfloat16_rn(v[j] - __bfloat162float(hh));
            }
            int off = r * 144 + q * 16;
            *(uint4*)(sm + SM_AHI + off) = H.u;
            *(uint4*)(sm + SM_ALO + off) = L.u;
        }
        // ---- B: preconverted bf16 hi/lo, K-major [n][k] ----------------------
        #pragma unroll
        for (int g = tid; g < 1024; g += 256) {
            int n = g >> 3, q = g & 7;
            long gb = (long)(head * Nw + n0 + n) * 256 + c * 64 + q * 8;
            uint4 vh = *(const uint4*)(Whi + gb);
            uint4 vl = *(const uint4*)(Wlo + gb);
            int off = n * 144 + q * 16;
            *(uint4*)(sm + SM_BHI + off) = vh;
            *(uint4*)(sm + SM_BLO + off) = vl;
        }
        __syncthreads();

        // ---- MMA over 4 k16 steps -------------------------------------------
        #pragma unroll
        for (int s = 0; s < 4; s++) {
            // B fragments: 4 n8-tiles (hi & lo)
            uint32_t Bh[4][2], Bl[4][2];
            #pragma unroll
            for (int p = 0; p < 2; p++) {
                // x4: sub0 = n rows+0-7 k+0, sub1 = rows+0-7 k+8,
                //     sub2 = rows+8  k+0, sub3 = rows+8  k+8
                int brow = warp_n * 32 + p * 16 + rin + ((sub >> 1) << 3);
                int bk = s * 16 + ((sub & 1) << 3);
                uint32_t addr = sb + SM_BHI + brow * 144 + bk * 2;
                uint32_t t4[4];
                ldsm4(t4, addr);
                Bh[2 * p][0] = t4[0]; Bh[2 * p][1] = t4[1];
                Bh[2 * p + 1][0] = t4[2]; Bh[2 * p + 1][1] = t4[3];
                ldsm4(t4, addr + (SM_BLO - SM_BHI));
                Bl[2 * p][0] = t4[0]; Bl[2 * p][1] = t4[1];
                Bl[2 * p + 1][0] = t4[2]; Bl[2 * p + 1][1] = t4[3];
            }
            #pragma unroll
            for (int mi = 0; mi < 4; mi++) {
                // A x4: sub0 = rows+0-7 k+0, sub1 = rows+8 k+0,
                //       sub2 = rows+0-7 k+8, sub3 = rows+8 k+8
                int arow = warp_m * 64 + mi * 16 + rin + ((sub & 1) << 3);
                int ak = s * 16 + ((sub >> 1) << 3);
                uint32_t addr = sb + SM_AHI + arow * 144 + ak * 2;
                uint32_t Ah[4], Al[4];
                ldsm4(Ah, addr);
                ldsm4(Al, addr + (SM_ALO - SM_AHI));
                #pragma unroll
                for (int ni = 0; ni < 4; ni++) {
                    mma16816(acc[mi][ni], Ah, Bh[ni]);
                    mma16816(acc[mi][ni], Ah, Bl[ni]);
                    mma16816(acc[mi][ni], Al, Bh[ni]);
                }
            }
        }
        __syncthreads();
    }

    // ---- epilogue: direct stores with bias -----------------------------------
    int g4 = lid >> 2, tg = lid & 3;
    #pragma unroll
    for (int mi = 0; mi < 4; mi++) {
        int r0 = tok0 + warp_m * 64 + mi * 16 + g4;
        #pragma unroll
        for (int ni = 0; ni < 4; ni++) {
            int ncol = n0 + warp_n * 32 + ni * 8 + tg * 2;
            float b0 = bias[head * Nw + ncol];
            float b1 = bias[head * Nw + ncol + 1];
            float2 o0 = make_float2(acc[mi][ni][0] + b0, acc[mi][ni][1] + b1);
            float2 o1 = make_float2(acc[mi][ni][2] + b0, acc[mi][ni][3] + b1);
            *(float2*)(out + ((long)r0 * 8 + head) * Nw + ncol) = o0;
            *(float2*)(out + ((long)(r0 + 8) * 8 + head) * Nw + ncol) = o1;
        }
    }
}

// ---------------- K5: LN over (H,3,DO)=3072 per token + gates -----------------
__global__ __launch_bounds__(256) void k_ln_gates(const float* __restrict__ gh,
                                                  const float* __restrict__ bh) {
    __shared__ float red[32];
    __shared__ float sm[3072];
    int t = blockIdx.x;
    int tid = threadIdx.x;
    float v[12];
    #pragma unroll
    for (int j = 0; j < 12; j++) v[j] = g_h3[(long)t * 3072 + tid + j * 256];
    float s1 = 0.0f;
    #pragma unroll
    for (int j = 0; j < 12; j++) s1 += v[j];
    s1 = blockSum256(s1, red);
    float mu = s1 * (1.0f / 3072.0f);
    float q = 0.0f;
    #pragma unroll
    for (int j = 0; j < 12; j++) { float d = v[j] - mu; q += d * d; }
    q = blockSum256(q, red);
    float rs = rsqrtf(q * (1.0f / 3072.0f) + 1e-6f);
    #pragma unroll
    for (int j = 0; j < 12; j++) {
        int e = tid + j * 256;
        sm[e] = (v[j] - mu) * rs * gh[e] + bh[e];
    }
    __syncthreads();
    #pragma unroll
    for (int j = 0; j < 4; j++) {
        int idx = tid + j * 256;          // n*128 + d
        int n = idx >> 7;
        int d = idx & 127;
        float ig = sm[n * 384 + d];
        float fg = sm[n * 384 + 128 + d];
        float hv = sm[n * 384 + 256 + d];
        g_fg[t * HD + idx]  = sigmoidf_(fg);
        g_igh[t * HD + idx] = sigmoidf_(ig) * fmaxf(hv, 0.0f);
    }
}

// ---------------- K6a/b/c: chunked linear-recurrence scan ---------------------
__global__ void k_scan_agg() {
    int gid = blockIdx.x * 256 + threadIdx.x;
    int lane = gid & 4095;
    int chunk = gid >> 12;
    int off = lane & 1023;
    int b = lane >> 10;
    int base = (b * SSEQ + chunk * CH) * HD + off;
    float F = 1.0f, I = 0.0f;
    #pragma unroll 4
    for (int i = 0; i < CH; i++) {
        int idx = base + i * HD;
        float f = g_fg[idx];
        I = f * I + g_igh[idx];
        F *= f;
    }
    g_aggF[gid] = F;
    g_aggI[gid] = I;
}
__global__ void k_scan_carry(const float* __restrict__ init_cx) {
    int lane = blockIdx.x * 256 + threadIdx.x;
    float c = init_cx[lane & 1023];
    #pragma unroll
    for (int chunk = 0; chunk < NCH; chunk++) {
        g_carry[chunk * 4096 + lane] = c;
        c = g_aggF[chunk * 4096 + lane] * c + g_aggI[chunk * 4096 + lane];
    }
}
__global__ void k_scan_apply() {
    int gid = blockIdx.x * 256 + threadIdx.x;
    int lane = gid & 4095;
    int chunk = gid >> 12;
    int off = lane & 1023;
    int b = lane >> 10;
    int base = (b * SSEQ + chunk * CH) * HD + off;
    float c = g_carry[gid];
    #pragma unroll 4
    for (int i = 0; i < CH; i++) {
        int idx = base + i * HD;
        c = g_fg[idx] * c + g_igh[idx];
        g_cell[idx] = c;
    }
}

// ---------------- K8: final LN over (H,DO)=1024 + sigmoid * cell --------------
__global__ __launch_bounds__(256) void k_final(const float* __restrict__ gog,
                                               const float* __restrict__ bog,
                                               float* __restrict__ out) {
    __shared__ float red[32];
    int t = blockIdx.x;
    int tid = threadIdx.x;
    float v[4];
    #pragma unroll
    for (int j = 0; j < 4; j++) v[j] = g_h3[(long)t * HD + tid + j * 256];
    float s1 = v[0] + v[1] + v[2] + v[3];
    s1 = blockSum256(s1, red);
    float mu = s1 * (1.0f / 1024.0f);
    float q = 0.0f;
    #pragma unroll
    for (int j = 0; j < 4; j++) { float d = v[j] - mu; q += d * d; }
    q = blockSum256(q, red);
    float rs = rsqrtf(q * (1.0f / 1024.0f) + 1e-6f);
    #pragma unroll
    for (int j = 0; j < 4; j++) {
        int idx = tid + j * 256;
        float og = (v[j] - mu) * rs * gog[idx] + bog[idx];
        out[t * HD + idx] = sigmoidf_(og) * g_cell[t * HD + idx];
    }
}

// ------------------------------------------------------------------------------
extern "C" void kernel_launch(void* const* d_in, const int* in_sizes, int n_in,
                              void* d_out, int out_size) {
    const float* hi        = (const float*)d_in[0];
    const float* W_hid     = (const float*)d_in[1];
    const float* b_hid     = (const float*)d_in[2];
    const float* gcsum     = (const float*)d_in[3];
    const float* bcsum     = (const float*)d_in[4];
    const float* g_hid     = (const float*)d_in[5];
    const float* beta_hid  = (const float*)d_in[6];
    const float* W_og      = (const float*)d_in[7];
    const float* b_og      = (const float*)d_in[8];
    const float* g_og      = (const float*)d_in[9];
    const float* beta_og   = (const float*)d_in[10];
    const float* init_cx   = (const float*)d_in[11];
    float* out = (float*)d_out;

    cudaFuncSetAttribute(k_gemm_mma, cudaFuncAttributeMaxDynamicSharedMemorySize, SM_GEMM);

    // device-global scratch pointers (resolved host-side via symbol addresses is
    // not allowed; kernels reference them directly)
    float* csum_p; cudaGetSymbolAddress((void**)&csum_p, g_csum);
    float* cell_p; cudaGetSymbolAddress((void**)&cell_p, g_cell);
    float* h3_p;   cudaGetSymbolAddress((void**)&h3_p,   g_h3);
    __nv_bfloat16 *wh_hi, *wh_lo, *wo_hi, *wo_lo;
    cudaGetSymbolAddress((void**)&wh_hi, g_Wh_hi);
    cudaGetSymbolAddress((void**)&wh_lo, g_Wh_lo);
    cudaGetSymbolAddress((void**)&wo_hi, g_Wo_hi);
    cudaGetSymbolAddress((void**)&wo_lo, g_Wo_lo);

    k_prepW1<<<3072, 256>>>(W_hid);
    k_prepW2<<<1024, 256>>>(W_og);
    k_cumsum<<<256, 256>>>(hi);
    k_scanoff<<<16, 256>>>();
    k_csum_ln<<<NTOK, 256>>>(gcsum, bcsum);
    k_gemm_mma<<<dim3(128, 3, 8), 256, SM_GEMM>>>(hi, csum_p, wh_hi, wh_lo,
                                                  b_hid, h3_p, 384);
    k_ln_gates<<<NTOK, 256>>>(g_hid, beta_hid);
    k_scan_agg<<<256, 256>>>();
    k_scan_carry<<<16, 256>>>(init_cx);
    k_scan_apply<<<256, 256>>>();
    k_gemm_mma<<<dim3(128, 1, 8), 256, SM_GEMM>>>(hi, cell_p, wo_hi, wo_lo,
                                                  b_og, h3_p, 128);
    k_final<<<NTOK, 256>>>(g_og, beta_og, out);
}

// round 8
// speedup vs baseline: 1.7297x; 1.0003x over previous
#include <cuda_runtime.h>
#include <cuda_bf16.h>
#include <cstdint>
#include <math.h>

// Problem constants
#define BB 4
#define SSEQ 4096
#define HH 8
#define DI 128
#define DOUT 128
#define HD 1024            // HH*DI
#define NTOK (BB*SSEQ)     // 16384
#define CHS 128            // scan chunk length
#define NCHS 32            // SSEQ / CHS

// ---------------- scratch (static device globals; no allocations) -------------
__device__ float g_csum[(long)NTOK * HD];    // exclusive cumsum, later normalized
__device__ float g_h3[(long)NTOK * HH * 384];// h3 raw; reused as og raw
__device__ float g_fg[(long)NTOK * HD];      // forget gate (sigmoid)
__device__ float g_igh[(long)NTOK * HD];     // sigmoid(i)*relu(h)
__device__ float g_cell[(long)NTOK * HD];    // scan output
__device__ float g_ctot[NCHS * BB * HD];     // [chunk][b][hd]
__device__ float g_coff[NCHS * BB * HD];
__device__ float g_aggF[NCHS * BB * HD];
__device__ float g_aggI[NCHS * BB * HD];
__device__ float g_carry[NCHS * BB * HD];

// bf16 hi/lo split weights, K-major ([head][n][k])
__device__ __nv_bfloat16 g_Wh_hi[8 * 384 * 256];
__device__ __nv_bfloat16 g_Wh_lo[8 * 384 * 256];
__device__ __nv_bfloat16 g_Wo_hi[8 * 128 * 256];
__device__ __nv_bfloat16 g_Wo_lo[8 * 128 * 256];

__device__ __forceinline__ float sigmoidf_(float x) {
    return 1.0f / (1.0f + expf(-x));
}

// ======================= mma.sync / ldmatrix helpers ==========================
__device__ __forceinline__ uint32_t s2u(const void* p) {
    uint32_t a;
    asm("{ .reg .u64 t; cvta.to.shared.u64 t, %1; cvt.u32.u64 %0, t; }" : "=r"(a) : "l"(p));
    return a;
}
__device__ __forceinline__ void ldsm4(uint32_t r[4], uint32_t addr) {
    asm volatile("ldmatrix.sync.aligned.m8n8.x4.shared.b16 {%0,%1,%2,%3}, [%4];"
                 : "=r"(r[0]), "=r"(r[1]), "=r"(r[2]), "=r"(r[3]) : "r"(addr));
}
__device__ __forceinline__ void mma16816(float* c, const uint32_t* a, const uint32_t* b) {
    asm volatile(
        "mma.sync.aligned.m16n8k16.row.col.f32.bf16.bf16.f32 "
        "{%0,%1,%2,%3}, {%4,%5,%6,%7}, {%8,%9}, {%0,%1,%2,%3};"
        : "+f"(c[0]), "+f"(c[1]), "+f"(c[2]), "+f"(c[3])
        : "r"(a[0]), "r"(a[1]), "r"(a[2]), "r"(a[3]), "r"(b[0]), "r"(b[1]));
}

// block-wide sum reduction (blockDim.x == 256), result broadcast
__device__ __forceinline__ float blockSum256(float v, float* red) {
    int tid = threadIdx.x;
    #pragma unroll
    for (int o = 16; o; o >>= 1) v += __shfl_xor_sync(0xffffffffu, v, o);
    if ((tid & 31) == 0) red[tid >> 5] = v;
    __syncthreads();
    if (tid < 32) {
        float x = (tid < 8) ? red[tid] : 0.0f;
        #pragma unroll
        for (int o = 4; o; o >>= 1) x += __shfl_xor_sync(0xffffffffu, x, o);
        if (tid == 0) red[0] = x;
    }
    __syncthreads();
    float r = red[0];
    __syncthreads();
    return r;
}

// ---------------- K1: per-chunk exclusive cumsum (float4 lanes) ---------------
__global__ __launch_bounds__(256) void k_cumsum(const float* __restrict__ hi) {
    int b = blockIdx.x >> 5, chunk = blockIdx.x & 31;
    int hd = threadIdx.x * 4;
    long base = ((long)(b * SSEQ + chunk * CHS)) * HD + hd;
    float4 run = make_float4(0.f, 0.f, 0.f, 0.f);
    #pragma unroll 4
    for (int i = 0; i < CHS; i++) {
        float4 v = *(const float4*)(hi + base + (long)i * HD);
        *(float4*)(g_csum + base + (long)i * HD) = run;
        run.x += v.x; run.y += v.y; run.z += v.z; run.w += v.w;
    }
    *(float4*)(g_ctot + (chunk * BB + b) * HD + hd) = run;
}

// ---------------- K2: scan chunk totals -> offsets ----------------------------
__global__ __launch_bounds__(256) void k_scanoff() {
    int gid = blockIdx.x * 256 + threadIdx.x;   // 0..1023
    int b = gid >> 8;
    int hd = (gid & 255) * 4;
    float4 run = make_float4(0.f, 0.f, 0.f, 0.f);
    #pragma unroll
    for (int c = 0; c < NCHS; c++) {
        float4 t = *(const float4*)(g_ctot + (c * BB + b) * HD + hd);
        *(float4*)(g_coff + (c * BB + b) * HD + hd) = run;
        run.x += t.x; run.y += t.y; run.z += t.z; run.w += t.w;
    }
}

// ---------------- K3: csum LayerNorm over (H,DI)=1024 per token ---------------
__global__ __launch_bounds__(256) void k_csum_ln(const float* __restrict__ gcs,
                                                 const float* __restrict__ bcs) {
    __shared__ float red[32];
    int t = blockIdx.x;
    int b = t >> 12;
    int chunk = (t & (SSEQ - 1)) >> 7;
    int tid = threadIdx.x;
    float v[4];
    #pragma unroll
    for (int j = 0; j < 4; j++) {
        int hd = tid + j * 256;
        v[j] = g_csum[(long)t * HD + hd] + g_coff[(chunk * BB + b) * HD + hd];
    }
    float s1 = v[0] + v[1] + v[2] + v[3];
    s1 = blockSum256(s1, red);
    float mu = s1 * (1.0f / 1024.0f);
    float q = 0.0f;
    #pragma unroll
    for (int j = 0; j < 4; j++) { float d = v[j] - mu; q += d * d; }
    q = blockSum256(q, red);
    float rs = rsqrtf(q * (1.0f / 1024.0f) + 1e-6f);
    #pragma unroll
    for (int j = 0; j < 4; j++) {
        int hd = tid + j * 256;
        g_csum[(long)t * HD + hd] = (v[j] - mu) * rs * gcs[hd] + bcs[hd];
    }
}

// ---------------- Weight prep: fp32 -> bf16 hi/lo, transpose to [h][n][k] -----
__global__ void k_prepW1(const float* __restrict__ W) {   // W_hid (8,256,384)
    int gid = blockIdx.x * 256 + threadIdx.x;             // h*256*384 + k*384 + n
    int n = gid % 384;
    int hk = gid / 384;
    int k = hk & 255;
    int h = hk >> 8;
    float v = W[gid];
    __nv_bfloat16 hh = __float2bfloat16_rn(v);
    __nv_bfloat16 ll = __float2bfloat16_rn(v - __bfloat162float(hh));
    int o = (h * 384 + n) * 256 + k;
    g_Wh_hi[o] = hh;
    g_Wh_lo[o] = ll;
}
__global__ void k_prepW2(const float* __restrict__ W) {   // W_og (8,256,128)
    int gid = blockIdx.x * 256 + threadIdx.x;             // h*32768 + k*128 + n
    int n = gid & 127;
    int k = (gid >> 7) & 255;
    int h = gid >> 15;
    float v = W[gid];
    __nv_bfloat16 hh = __float2bfloat16_rn(v);
    __nv_bfloat16 ll = __float2bfloat16_rn(v - __bfloat162float(hh));
    int o = (h * 128 + n) * 256 + k;
    g_Wo_hi[o] = hh;
    g_Wo_lo[o] = ll;
}

// ---------------- GEMM via mma.sync bf16 hi/lo emulation ----------------------
// CTA tile 128(M) x 128(N) per ntile; A (full K=256) SMEM-resident hi/lo,
// looped over nTiles N-tiles (3 for gemm1, 1 for gemm2) to reuse A.
// 256 threads = 8 warps in 2(m) x 4(n); warp tile 64x32; mma m16n8k16.
// A stride 264 elems (528 B), B stride 72 elems (144 B) -> LDSM conflict-free.
#define A_BYTES (128 * 264 * 2)          // 67584
#define B_BYTES (128 * 72 * 2)           // 18432
#define SM_AHI  0
#define SM_ALO  (A_BYTES)
#define SM_BHI  (2 * A_BYTES)
#define SM_BLO  (2 * A_BYTES + B_BYTES)
#define SM_GEMM (2 * A_BYTES + 2 * B_BYTES)  // 172032

__global__ __launch_bounds__(256, 1) void k_gemm_fused(
    const float* __restrict__ A1,        // K-half 0 source (heads_input)
    const float* __restrict__ A2,        // K-half 1 source (csum_n or cell)
    const __nv_bfloat16* __restrict__ Whi,
    const __nv_bfloat16* __restrict__ Wlo,
    const float* __restrict__ bias,
    float* __restrict__ out,
    int Nw, int nTiles)
{
    extern __shared__ char sm[];
    uint32_t sb = s2u(sm);
    int tid = threadIdx.x;
    int wid = tid >> 5, lid = tid & 31;
    int warp_m = wid >> 2, warp_n = wid & 3;
    int mtile = blockIdx.x, head = blockIdx.y;
    int tok0 = mtile * 128;
    int sub = lid >> 3, rin = lid & 7;

    // ---- A: full K=256, fp32 -> bf16 hi/lo into padded SMEM ------------------
    #pragma unroll 4
    for (int g = tid; g < 4096; g += 256) {     // 128 rows x 32 groups of 8
        int r = g >> 5, q = g & 31;
        const float* p = (q < 16)
            ? A1 + ((long)(tok0 + r) * 8 + head) * 128 + q * 8
            : A2 + ((long)(tok0 + r) * 8 + head) * 128 + (q - 16) * 8;
        float4 u0 = *(const float4*)p;
        float4 u1 = *(const float4*)(p + 4);
        float v[8] = {u0.x, u0.y, u0.z, u0.w, u1.x, u1.y, u1.z, u1.w};
        union { __nv_bfloat16 h[8]; uint4 u; } H, L;
        #pragma unroll
        for (int j = 0; j < 8; j++) {
            __nv_bfloat16 hh = __float2bfloat16_rn(v[j]);
            H.h[j] = hh;
            L.h[j] = __float2bfloat16_rn(v[j] - __bfloat162float(hh));
        }
        int off = r * 528 + q * 16;
        *(uint4*)(sm + SM_AHI + off) = H.u;
        *(uint4*)(sm + SM_ALO + off) = L.u;
    }
    __syncthreads();

    for (int nt = 0; nt < nTiles; nt++) {
        int n0 = nt * 128;
        float acc[4][4][4];
        #pragma unroll
        for (int i = 0; i < 4; i++)
            #pragma unroll
            for (int j = 0; j < 4; j++)
                #pragma unroll
                for (int e = 0; e < 4; e++) acc[i][j][e] = 0.0f;

        for (int c = 0; c < 4; c++) {
            // ---- B chunk (64 K-cols): preconverted bf16 hi/lo ----------------
            #pragma unroll
            for (int g = tid; g < 1024; g += 256) {
                int n = g >> 3, q = g & 7;
                long gb = (long)(head * Nw + n0 + n) * 256 + c * 64 + q * 8;
                uint4 vh = *(const uint4*)(Whi + gb);
                uint4 vl = *(const uint4*)(Wlo + gb);
                int off = n * 144 + q * 16;
                *(uint4*)(sm + SM_BHI + off) = vh;
                *(uint4*)(sm + SM_BLO + off) = vl;
            }
            __syncthreads();

            #pragma unroll
            for (int s = 0; s < 4; s++) {
                uint32_t Bh[4][2], Bl[4][2];
                #pragma unroll
                for (int p = 0; p < 2; p++) {
                    int brow = warp_n * 32 + p * 16 + rin + ((sub >> 1) << 3);
                    int bk = s * 16 + ((sub & 1) << 3);
                    uint32_t addr = sb + SM_BHI + brow * 144 + bk * 2;
                    uint32_t t4[4];
                    ldsm4(t4, addr);
                    Bh[2 * p][0] = t4[0]; Bh[2 * p][1] = t4[1];
                    Bh[2 * p + 1][0] = t4[2]; Bh[2 * p + 1][1] = t4[3];
                    ldsm4(t4, addr + (SM_BLO - SM_BHI));
                    Bl[2 * p][0] = t4[0]; Bl[2 * p][1] = t4[1];
                    Bl[2 * p + 1][0] = t4[2]; Bl[2 * p + 1][1] = t4[3];
                }
                #pragma unroll
                for (int mi = 0; mi < 4; mi++) {
                    int arow = warp_m * 64 + mi * 16 + rin + ((sub & 1) << 3);
                    int ak = c * 64 + s * 16 + ((sub >> 1) << 3);
                    uint32_t addr = sb + SM_AHI + arow * 528 + ak * 2;
                    uint32_t Ah[4], Al[4];
                    ldsm4(Ah, addr);
                    ldsm4(Al, addr + (SM_ALO - SM_AHI));
                    #pragma unroll
                    for (int ni = 0; ni < 4; ni++) {
                        mma16816(acc[mi][ni], Ah, Bh[ni]);
                        mma16816(acc[mi][ni], Ah, Bl[ni]);
                        mma16816(acc[mi][ni], Al, Bh[ni]);
                    }
                }
            }
            __syncthreads();
        }

        // ---- epilogue for this ntile: direct stores with bias ----------------
        int g4 = lid >> 2, tg = lid & 3;
        #pragma unroll
        for (int mi = 0; mi < 4; mi++) {
            int r0 = tok0 + warp_m * 64 + mi * 16 + g4;
            #pragma unroll
            for (int ni = 0; ni < 4; ni++) {
                int ncol = n0 + warp_n * 32 + ni * 8 + tg * 2;
                float b0 = bias[head * Nw + ncol];
                float b1 = bias[head * Nw + ncol + 1];
                float2 o0 = make_float2(acc[mi][ni][0] + b0, acc[mi][ni][1] + b1);
                float2 o1 = make_float2(acc[mi][ni][2] + b0, acc[mi][ni][3] + b1);
                *(float2*)(out + ((long)r0 * 8 + head) * Nw + ncol) = o0;
                *(float2*)(out + ((long)(r0 + 8) * 8 + head) * Nw + ncol) = o1;
            }
        }
    }
}

// ---------------- K5: LN over (H,3,DO)=3072 per token + gates -----------------
__global__ __launch_bounds__(256) void k_ln_gates(const float* __restrict__ gh,
                                                  const float* __restrict__ bh) {
    __shared__ float red[32];
    __shared__ float sm[3072];
    int t = blockIdx.x;
    int tid = threadIdx.x;
    float v[12];
    #pragma unroll
    for (int j = 0; j < 12; j++) v[j] = g_h3[(long)t * 3072 + tid + j * 256];
    float s1 = 0.0f;
    #pragma unroll
    for (int j = 0; j < 12; j++) s1 += v[j];
    s1 = blockSum256(s1, red);
    float mu = s1 * (1.0f / 3072.0f);
    float q = 0.0f;
    #pragma unroll
    for (int j = 0; j < 12; j++) { float d = v[j] - mu; q += d * d; }
    q = blockSum256(q, red);
    float rs = rsqrtf(q * (1.0f / 3072.0f) + 1e-6f);
    #pragma unroll
    for (int j = 0; j < 12; j++) {
        int e = tid + j * 256;
        sm[e] = (v[j] - mu) * rs * gh[e] + bh[e];
    }
    __syncthreads();
    #pragma unroll
    for (int j = 0; j < 4; j++) {
        int idx = tid + j * 256;          // n*128 + d
        int n = idx >> 7;
        int d = idx & 127;
        float ig = sm[n * 384 + d];
        float fg = sm[n * 384 + 128 + d];
        float hv = sm[n * 384 + 256 + d];
        g_fg[(long)t * HD + idx]  = sigmoidf_(fg);
        g_igh[(long)t * HD + idx] = sigmoidf_(ig) * fmaxf(hv, 0.0f);
    }
}

// ---------------- K6a/b/c: chunked linear-recurrence scan (float4 lanes) ------
__global__ __launch_bounds__(256) void k_scan_agg() {
    int b = blockIdx.x >> 5, chunk = blockIdx.x & 31;
    int hd = threadIdx.x * 4;
    long base = ((long)(b * SSEQ + chunk * CHS)) * HD + hd;
    float4 F = make_float4(1.f, 1.f, 1.f, 1.f);
    float4 I = make_float4(0.f, 0.f, 0.f, 0.f);
    #pragma unroll 4
    for (int i = 0; i < CHS; i++) {
        float4 f = *(const float4*)(g_fg + base + (long)i * HD);
        float4 g = *(const float4*)(g_igh + base + (long)i * HD);
        I.x = fmaf(f.x, I.x, g.x); I.y = fmaf(f.y, I.y, g.y);
        I.z = fmaf(f.z, I.z, g.z); I.w = fmaf(f.w, I.w, g.w);
        F.x *= f.x; F.y *= f.y; F.z *= f.z; F.w *= f.w;
    }
    *(float4*)(g_aggF + (chunk * BB + b) * HD + hd) = F;
    *(float4*)(g_aggI + (chunk * BB + b) * HD + hd) = I;
}
__global__ __launch_bounds__(256) void k_scan_carry(const float* __restrict__ init_cx) {
    int gid = blockIdx.x * 256 + threadIdx.x;   // 0..1023
    int b = gid >> 8;
    int hd = (gid & 255) * 4;
    float4 c = *(const float4*)(init_cx + hd);
    #pragma unroll
    for (int chunk = 0; chunk < NCHS; chunk++) {
        int o = (chunk * BB + b) * HD + hd;
        *(float4*)(g_carry + o) = c;
        float4 F = *(const float4*)(g_aggF + o);
        float4 I = *(const float4*)(g_aggI + o);
        c.x = fmaf(F.x, c.x, I.x); c.y = fmaf(F.y, c.y, I.y);
        c.z = fmaf(F.z, c.z, I.z); c.w = fmaf(F.w, c.w, I.w);
    }
}
__global__ __launch_bounds__(256) void k_scan_apply() {
    int b = blockIdx.x >> 5, chunk = blockIdx.x & 31;
    int hd = threadIdx.x * 4;
    long base = ((long)(b * SSEQ + chunk * CHS)) * HD + hd;
    float4 c = *(const float4*)(g_carry + (chunk * BB + b) * HD + hd);
    #pragma unroll 4
    for (int i = 0; i < CHS; i++) {
        float4 f = *(const float4*)(g_fg + base + (long)i * HD);
        float4 g = *(const float4*)(g_igh + base + (long)i * HD);
        c.x = fmaf(f.x, c.x, g.x); c.y = fmaf(f.y, c.y, g.y);
        c.z = fmaf(f.z, c.z, g.z); c.w = fmaf(f.w, c.w, g.w);
        *(float4*)(g_cell + base + (long)i * HD) = c;
    }
}

// ---------------- K8: final LN over (H,DO)=1024 + sigmoid * cell --------------
__global__ __launch_bounds__(256) void k_final(const float* __restrict__ gog,
                                               const float* __restrict__ bog,
                                               float* __restrict__ out) {
    __shared__ float red[32];
    int t = blockIdx.x;
    int tid = threadIdx.x;
    float v[4];
    #pragma unroll
    for (int j = 0; j < 4; j++) v[j] = g_h3[(long)t * HD + tid + j * 256];
    float s1 = v[0] + v[1] + v[2] + v[3];
    s1 = blockSum256(s1, red);
    float mu = s1 * (1.0f / 1024.0f);
    float q = 0.0f;
    #pragma unroll
    for (int j = 0; j < 4; j++) { float d = v[j] - mu; q += d * d; }
    q = blockSum256(q, red);
    float rs = rsqrtf(q * (1.0f / 1024.0f) + 1e-6f);
    #pragma unroll
    for (int j = 0; j < 4; j++) {
        int idx = tid + j * 256;
        float og = (v[j] - mu) * rs * gog[idx] + bog[idx];
        out[(long)t * HD + idx] = sigmoidf_(og) * g_cell[(long)t * HD + idx];
    }
}

// ------------------------------------------------------------------------------
extern "C" void kernel_launch(void* const* d_in, const int* in_sizes, int n_in,
                              void* d_out, int out_size) {
    const float* hi        = (const float*)d_in[0];
    const float* W_hid     = (const float*)d_in[1];
    const float* b_hid     = (const float*)d_in[2];
    const float* gcsum     = (const float*)d_in[3];
    const float* bcsum     = (const float*)d_in[4];
    const float* g_hid     = (const float*)d_in[5];
    const float* beta_hid  = (const float*)d_in[6];
    const float* W_og      = (const float*)d_in[7];
    const float* b_og      = (const float*)d_in[8];
    const float* g_og      = (const float*)d_in[9];
    const float* beta_og   = (const float*)d_in[10];
    const float* init_cx   = (const float*)d_in[11];
    float* out = (float*)d_out;

    cudaFuncSetAttribute(k_gemm_fused, cudaFuncAttributeMaxDynamicSharedMemorySize, SM_GEMM);

    float* csum_p; cudaGetSymbolAddress((void**)&csum_p, g_csum);
    float* cell_p; cudaGetSymbolAddress((void**)&cell_p, g_cell);
    float* h3_p;   cudaGetSymbolAddress((void**)&h3_p,   g_h3);
    __nv_bfloat16 *wh_hi, *wh_lo, *wo_hi, *wo_lo;
    cudaGetSymbolAddress((void**)&wh_hi, g_Wh_hi);
    cudaGetSymbolAddress((void**)&wh_lo, g_Wh_lo);
    cudaGetSymbolAddress((void**)&wo_hi, g_Wo_hi);
    cudaGetSymbolAddress((void**)&wo_lo, g_Wo_lo);

    k_prepW1<<<3072, 256>>>(W_hid);
    k_prepW2<<<1024, 256>>>(W_og);
    k_cumsum<<<128, 256>>>(hi);
    k_scanoff<<<4, 256>>>();
    k_csum_ln<<<NTOK, 256>>>(gcsum, bcsum);
    k_gemm_fused<<<dim3(128, 8), 256, SM_GEMM>>>(hi, csum_p, wh_hi, wh_lo,
                                                 b_hid, h3_p, 384, 3);
    k_ln_gates<<<NTOK, 256>>>(g_hid, beta_hid);
    k_scan_agg<<<128, 256>>>();
    k_scan_carry<<<4, 256>>>(init_cx);
    k_scan_apply<<<128, 256>>>();
    k_gemm_fused<<<dim3(128, 8), 256, SM_GEMM>>>(hi, cell_p, wo_hi, wo_lo,
                                                 b_og, h3_p, 128, 1);
    k_final<<<NTOK, 256>>>(g_og, beta_og, out);
}

// round 9
// speedup vs baseline: 1.9603x; 1.1333x over previous
#include <cuda_runtime.h>
#include <cuda_bf16.h>
#include <cstdint>
#include <math.h>

// Problem constants
#define BB 4
#define SSEQ 4096
#define HH 8
#define DI 128
#define DOUT 128
#define HD 1024            // HH*DI
#define NTOK (BB*SSEQ)     // 16384
#define CHS 32             // scan chunk length
#define NCHS 128           // SSEQ / CHS

// ---------------- scratch (static device globals; no allocations) -------------
__device__ float g_csum[(long)NTOK * HD];    // exclusive cumsum, later normalized
__device__ float g_h3[(long)NTOK * HH * 384];// h3 raw; reused as og raw
__device__ float g_fg[(long)NTOK * HD];      // forget gate (sigmoid)
__device__ float g_igh[(long)NTOK * HD];     // sigmoid(i)*relu(h)
__device__ float g_cell[(long)NTOK * HD];    // scan output
__device__ float g_ctot[NCHS * BB * HD];     // [chunk][b][hd]
__device__ float g_coff[NCHS * BB * HD];
__device__ float g_aggF[NCHS * BB * HD];
__device__ float g_aggI[NCHS * BB * HD];
__device__ float g_carry[NCHS * BB * HD];

// bf16 hi/lo split weights, K-major ([head][n][k])
__device__ __nv_bfloat16 g_Wh_hi[8 * 384 * 256];
__device__ __nv_bfloat16 g_Wh_lo[8 * 384 * 256];
__device__ __nv_bfloat16 g_Wo_hi[8 * 128 * 256];
__device__ __nv_bfloat16 g_Wo_lo[8 * 128 * 256];

__device__ __forceinline__ float sigmoidf_(float x) {
    return 1.0f / (1.0f + expf(-x));
}

// ======================= mma.sync / ldmatrix helpers ==========================
__device__ __forceinline__ uint32_t s2u(const void* p) {
    uint32_t a;
    asm("{ .reg .u64 t; cvta.to.shared.u64 t, %1; cvt.u32.u64 %0, t; }" : "=r"(a) : "l"(p));
    return a;
}
__device__ __forceinline__ void ldsm4(uint32_t r[4], uint32_t addr) {
    asm volatile("ldmatrix.sync.aligned.m8n8.x4.shared.b16 {%0,%1,%2,%3}, [%4];"
                 : "=r"(r[0]), "=r"(r[1]), "=r"(r[2]), "=r"(r[3]) : "r"(addr));
}
__device__ __forceinline__ void mma16816(float* c, const uint32_t* a, const uint32_t* b) {
    asm volatile(
        "mma.sync.aligned.m16n8k16.row.col.f32.bf16.bf16.f32 "
        "{%0,%1,%2,%3}, {%4,%5,%6,%7}, {%8,%9}, {%0,%1,%2,%3};"
        : "+f"(c[0]), "+f"(c[1]), "+f"(c[2]), "+f"(c[3])
        : "r"(a[0]), "r"(a[1]), "r"(a[2]), "r"(a[3]), "r"(b[0]), "r"(b[1]));
}

// block-wide sum reduction (blockDim.x == 256), result broadcast
__device__ __forceinline__ float blockSum256(float v, float* red) {
    int tid = threadIdx.x;
    #pragma unroll
    for (int o = 16; o; o >>= 1) v += __shfl_xor_sync(0xffffffffu, v, o);
    if ((tid & 31) == 0) red[tid >> 5] = v;
    __syncthreads();
    if (tid < 32) {
        float x = (tid < 8) ? red[tid] : 0.0f;
        #pragma unroll
        for (int o = 4; o; o >>= 1) x += __shfl_xor_sync(0xffffffffu, x, o);
        if (tid == 0) red[0] = x;
    }
    __syncthreads();
    float r = red[0];
    __syncthreads();
    return r;
}

// ---------------- Weight prep (fused): fp32 -> bf16 hi/lo, [h][n][k] ----------
__global__ void k_prepW(const float* __restrict__ W1, const float* __restrict__ W2) {
    int gid = blockIdx.x * 256 + threadIdx.x;
    if (gid < 8 * 256 * 384) {                 // W_hid (8,256,384)
        int n = gid % 384;
        int hk = gid / 384;
        int k = hk & 255;
        int h = hk >> 8;
        float v = W1[gid];
        __nv_bfloat16 hh = __float2bfloat16_rn(v);
        __nv_bfloat16 ll = __float2bfloat16_rn(v - __bfloat162float(hh));
        int o = (h * 384 + n) * 256 + k;
        g_Wh_hi[o] = hh;
        g_Wh_lo[o] = ll;
    } else {                                   // W_og (8,256,128)
        int g2 = gid - 8 * 256 * 384;
        int n = g2 & 127;
        int k = (g2 >> 7) & 255;
        int h = g2 >> 15;
        float v = W2[g2];
        __nv_bfloat16 hh = __float2bfloat16_rn(v);
        __nv_bfloat16 ll = __float2bfloat16_rn(v - __bfloat162float(hh));
        int o = (h * 128 + n) * 256 + k;
        g_Wo_hi[o] = hh;
        g_Wo_lo[o] = ll;
    }
}

// ---------------- K1: per-chunk exclusive cumsum (float4, MLP-4) --------------
__global__ __launch_bounds__(256) void k_cumsum(const float* __restrict__ hi) {
    int b = blockIdx.x >> 7, chunk = blockIdx.x & 127;
    int hd = threadIdx.x * 4;
    long base = ((long)(b * SSEQ + chunk * CHS)) * HD + hd;
    float4 run = make_float4(0.f, 0.f, 0.f, 0.f);
    #pragma unroll
    for (int i0 = 0; i0 < CHS; i0 += 4) {
        float4 v0 = *(const float4*)(hi + base + (long)(i0 + 0) * HD);
        float4 v1 = *(const float4*)(hi + base + (long)(i0 + 1) * HD);
        float4 v2 = *(const float4*)(hi + base + (long)(i0 + 2) * HD);
        float4 v3 = *(const float4*)(hi + base + (long)(i0 + 3) * HD);
        *(float4*)(g_csum + base + (long)(i0 + 0) * HD) = run;
        run.x += v0.x; run.y += v0.y; run.z += v0.z; run.w += v0.w;
        *(float4*)(g_csum + base + (long)(i0 + 1) * HD) = run;
        run.x += v1.x; run.y += v1.y; run.z += v1.z; run.w += v1.w;
        *(float4*)(g_csum + base + (long)(i0 + 2) * HD) = run;
        run.x += v2.x; run.y += v2.y; run.z += v2.z; run.w += v2.w;
        *(float4*)(g_csum + base + (long)(i0 + 3) * HD) = run;
        run.x += v3.x; run.y += v3.y; run.z += v3.z; run.w += v3.w;
    }
    *(float4*)(g_ctot + (chunk * BB + b) * HD + hd) = run;
}

// ---------------- K2: scan chunk totals -> offsets ----------------------------
__global__ __launch_bounds__(256) void k_scanoff() {
    int gid = blockIdx.x * 256 + threadIdx.x;   // 0..1023
    int b = gid >> 8;
    int hd = (gid & 255) * 4;
    float4 run = make_float4(0.f, 0.f, 0.f, 0.f);
    #pragma unroll 8
    for (int c = 0; c < NCHS; c++) {
        float4 t = *(const float4*)(g_ctot + (c * BB + b) * HD + hd);
        *(float4*)(g_coff + (c * BB + b) * HD + hd) = run;
        run.x += t.x; run.y += t.y; run.z += t.z; run.w += t.w;
    }
}

// ---------------- K3: csum LayerNorm over (H,DI)=1024 per token ---------------
__global__ __launch_bounds__(256) void k_csum_ln(const float* __restrict__ gcs,
                                                 const float* __restrict__ bcs) {
    __shared__ float red[32];
    int t = blockIdx.x;
    int b = t >> 12;
    int chunk = (t & (SSEQ - 1)) >> 5;
    int tid = threadIdx.x;
    float v[4];
    #pragma unroll
    for (int j = 0; j < 4; j++) {
        int hd = tid + j * 256;
        v[j] = g_csum[(long)t * HD + hd] + g_coff[(chunk * BB + b) * HD + hd];
    }
    float s1 = v[0] + v[1] + v[2] + v[3];
    s1 = blockSum256(s1, red);
    float mu = s1 * (1.0f / 1024.0f);
    float q = 0.0f;
    #pragma unroll
    for (int j = 0; j < 4; j++) { float d = v[j] - mu; q += d * d; }
    q = blockSum256(q, red);
    float rs = rsqrtf(q * (1.0f / 1024.0f) + 1e-6f);
    #pragma unroll
    for (int j = 0; j < 4; j++) {
        int hd = tid + j * 256;
        g_csum[(long)t * HD + hd] = (v[j] - mu) * rs * gcs[hd] + bcs[hd];
    }
}

// ---------------- GEMM via mma.sync bf16 hi/lo emulation ----------------------
// CTA tile 64(M) x 128(N); A (full K=256) SMEM-resident hi/lo, looped over
// nTiles N-tiles (3 for gemm1, 1 for gemm2). 2 CTAs/SM (104.4 KB SMEM).
// 256 threads = 8 warps in 2(m) x 4(n); warp tile 32x32; mma m16n8k16.
// A stride 264 elems (528 B), B stride 72 elems (144 B) -> LDSM conflict-free.
#define GA_BYTES (64 * 264 * 2)          // 33792 per A tile
#define GB_BYTES (128 * 72 * 2)          // 18432 per B tile
#define SM_AHI  0
#define SM_ALO  (GA_BYTES)
#define SM_BHI  (2 * GA_BYTES)
#define SM_BLO  (2 * GA_BYTES + GB_BYTES)
#define SM_GEMM (2 * GA_BYTES + 2 * GB_BYTES)  // 104448

__global__ __launch_bounds__(256, 2) void k_gemm_fused(
    const float* __restrict__ A1,        // K-half 0 source (heads_input)
    const float* __restrict__ A2,        // K-half 1 source (csum_n or cell)
    const __nv_bfloat16* __restrict__ Whi,
    const __nv_bfloat16* __restrict__ Wlo,
    const float* __restrict__ bias,
    float* __restrict__ out,
    int Nw, int nTiles)
{
    extern __shared__ char sm[];
    uint32_t sb = s2u(sm);
    int tid = threadIdx.x;
    int wid = tid >> 5, lid = tid & 31;
    int warp_m = wid >> 2, warp_n = wid & 3;
    int mtile = blockIdx.x, head = blockIdx.y;
    int tok0 = mtile * 64;
    int sub = lid >> 3, rin = lid & 7;

    // ---- A: full K=256 for 64 tokens, fp32 -> bf16 hi/lo ---------------------
    #pragma unroll
    for (int g = tid; g < 2048; g += 256) {     // 64 rows x 32 groups of 8
        int r = g >> 5, q = g & 31;
        const float* p = (q < 16)
            ? A1 + ((long)(tok0 + r) * 8 + head) * 128 + q * 8
            : A2 + ((long)(tok0 + r) * 8 + head) * 128 + (q - 16) * 8;
        float4 u0 = *(const float4*)p;
        float4 u1 = *(const float4*)(p + 4);
        float v[8] = {u0.x, u0.y, u0.z, u0.w, u1.x, u1.y, u1.z, u1.w};
        union { __nv_bfloat16 h[8]; uint4 u; } H, L;
        #pragma unroll
        for (int j = 0; j < 8; j++) {
            __nv_bfloat16 hh = __float2bfloat16_rn(v[j]);
            H.h[j] = hh;
            L.h[j] = __float2bfloat16_rn(v[j] - __bfloat162float(hh));
        }
        int off = r * 528 + q * 16;
        *(uint4*)(sm + SM_AHI + off) = H.u;
        *(uint4*)(sm + SM_ALO + off) = L.u;
    }
    __syncthreads();

    for (int nt = 0; nt < nTiles; nt++) {
        int n0 = nt * 128;
        float acc[2][4][4];
        #pragma unroll
        for (int i = 0; i < 2; i++)
            #pragma unroll
            for (int j = 0; j < 4; j++)
                #pragma unroll
                for (int e = 0; e < 4; e++) acc[i][j][e] = 0.0f;

        for (int c = 0; c < 4; c++) {
            // ---- B chunk (64 K-cols): preconverted bf16 hi/lo ----------------
            #pragma unroll
            for (int g = tid; g < 1024; g += 256) {
                int n = g >> 3, q = g & 7;
                long gb = (long)(head * Nw + n0 + n) * 256 + c * 64 + q * 8;
                uint4 vh = *(const uint4*)(Whi + gb);
                uint4 vl = *(const uint4*)(Wlo + gb);
                int off = n * 144 + q * 16;
                *(uint4*)(sm + SM_BHI + off) = vh;
                *(uint4*)(sm + SM_BLO + off) = vl;
            }
            __syncthreads();

            #pragma unroll
            for (int s = 0; s < 4; s++) {
                uint32_t Bh[4][2], Bl[4][2];
                #pragma unroll
                for (int p = 0; p < 2; p++) {
                    int brow = warp_n * 32 + p * 16 + rin + ((sub >> 1) << 3);
                    int bk = s * 16 + ((sub & 1) << 3);
                    uint32_t addr = sb + SM_BHI + brow * 144 + bk * 2;
                    uint32_t t4[4];
                    ldsm4(t4, addr);
                    Bh[2 * p][0] = t4[0]; Bh[2 * p][1] = t4[1];
                    Bh[2 * p + 1][0] = t4[2]; Bh[2 * p + 1][1] = t4[3];
                    ldsm4(t4, addr + (SM_BLO - SM_BHI));
                    Bl[2 * p][0] = t4[0]; Bl[2 * p][1] = t4[1];
                    Bl[2 * p + 1][0] = t4[2]; Bl[2 * p + 1][1] = t4[3];
                }
                #pragma unroll
                for (int mi = 0; mi < 2; mi++) {
                    int arow = warp_m * 32 + mi * 16 + rin + ((sub & 1) << 3);
                    int ak = c * 64 + s * 16 + ((sub >> 1) << 3);
                    uint32_t addr = sb + SM_AHI + arow * 528 + ak * 2;
                    uint32_t Ah[4], Al[4];
                    ldsm4(Ah, addr);
                    ldsm4(Al, addr + (SM_ALO - SM_AHI));
                    #pragma unroll
                    for (int ni = 0; ni < 4; ni++) {
                        mma16816(acc[mi][ni], Ah, Bh[ni]);
                        mma16816(acc[mi][ni], Ah, Bl[ni]);
                        mma16816(acc[mi][ni], Al, Bh[ni]);
                    }
                }
            }
            __syncthreads();
        }

        // ---- epilogue for this ntile: direct stores with bias ----------------
        int g4 = lid >> 2, tg = lid & 3;
        #pragma unroll
        for (int mi = 0; mi < 2; mi++) {
            int r0 = tok0 + warp_m * 32 + mi * 16 + g4;
            #pragma unroll
            for (int ni = 0; ni < 4; ni++) {
                int ncol = n0 + warp_n * 32 + ni * 8 + tg * 2;
                float b0 = bias[head * Nw + ncol];
                float b1 = bias[head * Nw + ncol + 1];
                float2 o0 = make_float2(acc[mi][ni][0] + b0, acc[mi][ni][1] + b1);
                float2 o1 = make_float2(acc[mi][ni][2] + b0, acc[mi][ni][3] + b1);
                *(float2*)(out + ((long)r0 * 8 + head) * Nw + ncol) = o0;
                *(float2*)(out + ((long)(r0 + 8) * 8 + head) * Nw + ncol) = o1;
            }
        }
    }
}

// ---------------- K5: LN over (H,3,DO)=3072 per token + gates -----------------
__global__ __launch_bounds__(256) void k_ln_gates(const float* __restrict__ gh,
                                                  const float* __restrict__ bh) {
    __shared__ float red[32];
    __shared__ float sm[3072];
    int t = blockIdx.x;
    int tid = threadIdx.x;
    float v[12];
    #pragma unroll
    for (int j = 0; j < 12; j++) v[j] = g_h3[(long)t * 3072 + tid + j * 256];
    float s1 = 0.0f;
    #pragma unroll
    for (int j = 0; j < 12; j++) s1 += v[j];
    s1 = blockSum256(s1, red);
    float mu = s1 * (1.0f / 3072.0f);
    float q = 0.0f;
    #pragma unroll
    for (int j = 0; j < 12; j++) { float d = v[j] - mu; q += d * d; }
    q = blockSum256(q, red);
    float rs = rsqrtf(q * (1.0f / 3072.0f) + 1e-6f);
    #pragma unroll
    for (int j = 0; j < 12; j++) {
        int e = tid + j * 256;
        sm[e] = (v[j] - mu) * rs * gh[e] + bh[e];
    }
    __syncthreads();
    #pragma unroll
    for (int j = 0; j < 4; j++) {
        int idx = tid + j * 256;          // n*128 + d
        int n = idx >> 7;
        int d = idx & 127;
        float ig = sm[n * 384 + d];
        float fg = sm[n * 384 + 128 + d];
        float hv = sm[n * 384 + 256 + d];
        g_fg[(long)t * HD + idx]  = sigmoidf_(fg);
        g_igh[(long)t * HD + idx] = sigmoidf_(ig) * fmaxf(hv, 0.0f);
    }
}

// ---------------- K6a/b/c: chunked linear-recurrence scan (float4, MLP-4) -----
__global__ __launch_bounds__(256) void k_scan_agg() {
    int b = blockIdx.x >> 7, chunk = blockIdx.x & 127;
    int hd = threadIdx.x * 4;
    long base = ((long)(b * SSEQ + chunk * CHS)) * HD + hd;
    float4 F = make_float4(1.f, 1.f, 1.f, 1.f);
    float4 I = make_float4(0.f, 0.f, 0.f, 0.f);
    #pragma unroll
    for (int i0 = 0; i0 < CHS; i0 += 4) {
        float4 f[4], g[4];
        #pragma unroll
        for (int u = 0; u < 4; u++) {
            f[u] = *(const float4*)(g_fg + base + (long)(i0 + u) * HD);
            g[u] = *(const float4*)(g_igh + base + (long)(i0 + u) * HD);
        }
        #pragma unroll
        for (int u = 0; u < 4; u++) {
            I.x = fmaf(f[u].x, I.x, g[u].x); I.y = fmaf(f[u].y, I.y, g[u].y);
            I.z = fmaf(f[u].z, I.z, g[u].z); I.w = fmaf(f[u].w, I.w, g[u].w);
            F.x *= f[u].x; F.y *= f[u].y; F.z *= f[u].z; F.w *= f[u].w;
        }
    }
    *(float4*)(g_aggF + (chunk * BB + b) * HD + hd) = F;
    *(float4*)(g_aggI + (chunk * BB + b) * HD + hd) = I;
}
__global__ __launch_bounds__(256) void k_scan_carry(const float* __restrict__ init_cx) {
    int gid = blockIdx.x * 256 + threadIdx.x;   // 0..1023
    int b = gid >> 8;
    int hd = (gid & 255) * 4;
    float4 c = *(const float4*)(init_cx + hd);
    #pragma unroll 8
    for (int chunk = 0; chunk < NCHS; chunk++) {
        int o = (chunk * BB + b) * HD + hd;
        *(float4*)(g_carry + o) = c;
        float4 F = *(const float4*)(g_aggF + o);
        float4 I = *(const float4*)(g_aggI + o);
        c.x = fmaf(F.x, c.x, I.x); c.y = fmaf(F.y, c.y, I.y);
        c.z = fmaf(F.z, c.z, I.z); c.w = fmaf(F.w, c.w, I.w);
    }
}
__global__ __launch_bounds__(256) void k_scan_apply() {
    int b = blockIdx.x >> 7, chunk = blockIdx.x & 127;
    int hd = threadIdx.x * 4;
    long base = ((long)(b * SSEQ + chunk * CHS)) * HD + hd;
    float4 c = *(const float4*)(g_carry + (chunk * BB + b) * HD + hd);
    #pragma unroll
    for (int i0 = 0; i0 < CHS; i0 += 4) {
        float4 f[4], g[4];
        #pragma unroll
        for (int u = 0; u < 4; u++) {
            f[u] = *(const float4*)(g_fg + base + (long)(i0 + u) * HD);
            g[u] = *(const float4*)(g_igh + base + (long)(i0 + u) * HD);
        }
        #pragma unroll
        for (int u = 0; u < 4; u++) {
            c.x = fmaf(f[u].x, c.x, g[u].x); c.y = fmaf(f[u].y, c.y, g[u].y);
            c.z = fmaf(f[u].z, c.z, g[u].z); c.w = fmaf(f[u].w, c.w, g[u].w);
            *(float4*)(g_cell + base + (long)(i0 + u) * HD) = c;
        }
    }
}

// ---------------- K8: final LN over (H,DO)=1024 + sigmoid * cell --------------
__global__ __launch_bounds__(256) void k_final(const float* __restrict__ gog,
                                               const float* __restrict__ bog,
                                               float* __restrict__ out) {
    __shared__ float red[32];
    int t = blockIdx.x;
    int tid = threadIdx.x;
    float v[4];
    #pragma unroll
    for (int j = 0; j < 4; j++) v[j] = g_h3[(long)t * HD + tid + j * 256];
    float s1 = v[0] + v[1] + v[2] + v[3];
    s1 = blockSum256(s1, red);
    float mu = s1 * (1.0f / 1024.0f);
    float q = 0.0f;
    #pragma unroll
    for (int j = 0; j < 4; j++) { float d = v[j] - mu; q += d * d; }
    q = blockSum256(q, red);
    float rs = rsqrtf(q * (1.0f / 1024.0f) + 1e-6f);
    #pragma unroll
    for (int j = 0; j < 4; j++) {
        int idx = tid + j * 256;
        float og = (v[j] - mu) * rs * gog[idx] + bog[idx];
        out[(long)t * HD + idx] = sigmoidf_(og) * g_cell[(long)t * HD + idx];
    }
}

// ------------------------------------------------------------------------------
extern "C" void kernel_launch(void* const* d_in, const int* in_sizes, int n_in,
                              void* d_out, int out_size) {
    const float* hi        = (const float*)d_in[0];
    const float* W_hid     = (const float*)d_in[1];
    const float* b_hid     = (const float*)d_in[2];
    const float* gcsum     = (const float*)d_in[3];
    const float* bcsum     = (const float*)d_in[4];
    const float* g_hid     = (const float*)d_in[5];
    const float* beta_hid  = (const float*)d_in[6];
    const float* W_og      = (const float*)d_in[7];
    const float* b_og      = (const float*)d_in[8];
    const float* g_og      = (const float*)d_in[9];
    const float* beta_og   = (const float*)d_in[10];
    const float* init_cx   = (const float*)d_in[11];
    float* out = (float*)d_out;

    cudaFuncSetAttribute(k_gemm_fused, cudaFuncAttributeMaxDynamicSharedMemorySize, SM_GEMM);

    float* csum_p; cudaGetSymbolAddress((void**)&csum_p, g_csum);
    float* cell_p; cudaGetSymbolAddress((void**)&cell_p, g_cell);
    float* h3_p;   cudaGetSymbolAddress((void**)&h3_p,   g_h3);
    __nv_bfloat16 *wh_hi, *wh_lo, *wo_hi, *wo_lo;
    cudaGetSymbolAddress((void**)&wh_hi, g_Wh_hi);
    cudaGetSymbolAddress((void**)&wh_lo, g_Wh_lo);
    cudaGetSymbolAddress((void**)&wo_hi, g_Wo_hi);
    cudaGetSymbolAddress((void**)&wo_lo, g_Wo_lo);

    k_prepW<<<4096, 256>>>(W_hid, W_og);                 // 0
    k_cumsum<<<512, 256>>>(hi);                          // 1
    k_scanoff<<<4, 256>>>();                             // 2
    k_csum_ln<<<NTOK, 256>>>(gcsum, bcsum);              // 3  <- ncu slot
    k_gemm_fused<<<dim3(256, 8), 256, SM_GEMM>>>(hi, csum_p, wh_hi, wh_lo,
                                                 b_hid, h3_p, 384, 3);
    k_ln_gates<<<NTOK, 256>>>(g_hid, beta_hid);
    k_scan_agg<<<512, 256>>>();
    k_scan_carry<<<4, 256>>>(init_cx);
    k_scan_apply<<<512, 256>>>();
    k_gemm_fused<<<dim3(256, 8), 256, SM_GEMM>>>(hi, cell_p, wo_hi, wo_lo,
                                                 b_og, h3_p, 128, 1);
    k_final<<<NTOK, 256>>>(g_og, beta_og, out);
}

// round 13
// speedup vs baseline: 1.9944x; 1.0174x over previous
#include <cuda_runtime.h>
#include <cuda_bf16.h>
#include <cstdint>
#include <math.h>

// Problem constants
#define BB 4
#define SSEQ 4096
#define HH 8
#define DI 128
#define DOUT 128
#define HD 1024            // HH*DI
#define NTOK (BB*SSEQ)     // 16384
#define CHS 32             // scan / cumsum chunk length
#define NCHS 128           // SSEQ / CHS

// ---------------- scratch (static device globals; no allocations) -------------
__device__ float g_h3[(long)NTOK * HH * 384];// h3 raw; reused as og raw
__device__ float g_fg[(long)NTOK * HD];      // forget gate (sigmoid)
__device__ float g_igh[(long)NTOK * HD];     // sigmoid(i)*relu(h)
__device__ float g_cell[(long)NTOK * HD];    // scan output
__device__ float g_ctot[NCHS * BB * HD];     // [chunk][b][hd] cumsum chunk totals
__device__ float g_coff[NCHS * BB * HD];     // exclusive chunk offsets
__device__ float g_aggF[NCHS * BB * HD];
__device__ float g_aggI[NCHS * BB * HD];
__device__ float g_carry[NCHS * BB * HD];
__device__ float2 g_stat[NTOK];              // (mu, rs) of csum-LN per token

// bf16 hi/lo split weights, K-major ([head][n][k])
__device__ __nv_bfloat16 g_Wh_hi[8 * 384 * 256];
__device__ __nv_bfloat16 g_Wh_lo[8 * 384 * 256];
__device__ __nv_bfloat16 g_Wo_hi[8 * 128 * 256];
__device__ __nv_bfloat16 g_Wo_lo[8 * 128 * 256];

// fast sigmoid via HW tanh: sigmoid(x) = 0.5*tanh(x/2)+0.5
__device__ __forceinline__ float sigmoidf_(float x) {
    float t;
    asm("tanh.approx.f32 %0, %1;" : "=f"(t) : "f"(0.5f * x));
    return fmaf(0.5f, t, 0.5f);
}

// ======================= mma.sync / ldmatrix helpers ==========================
__device__ __forceinline__ uint32_t s2u(const void* p) {
    uint32_t a;
    asm("{ .reg .u64 t; cvta.to.shared.u64 t, %1; cvt.u32.u64 %0, t; }" : "=r"(a) : "l"(p));
    return a;
}
__device__ __forceinline__ void ldsm4(uint32_t r[4], uint32_t addr) {
    asm volatile("ldmatrix.sync.aligned.m8n8.x4.shared.b16 {%0,%1,%2,%3}, [%4];"
                 : "=r"(r[0]), "=r"(r[1]), "=r"(r[2]), "=r"(r[3]) : "r"(addr));
}
__device__ __forceinline__ void mma16816(float* c, const uint32_t* a, const uint32_t* b) {
    asm volatile(
        "mma.sync.aligned.m16n8k16.row.col.f32.bf16.bf16.f32 "
        "{%0,%1,%2,%3}, {%4,%5,%6,%7}, {%8,%9}, {%0,%1,%2,%3};"
        : "+f"(c[0]), "+f"(c[1]), "+f"(c[2]), "+f"(c[3])
        : "r"(a[0]), "r"(a[1]), "r"(a[2]), "r"(a[3]), "r"(b[0]), "r"(b[1]));
}

// block-wide sum reduction (blockDim.x == 256), result broadcast
__device__ __forceinline__ float blockSum256(float v, float* red) {
    int tid = threadIdx.x;
    #pragma unroll
    for (int o = 16; o; o >>= 1) v += __shfl_xor_sync(0xffffffffu, v, o);
    if ((tid & 31) == 0) red[tid >> 5] = v;
    __syncthreads();
    if (tid < 32) {
        float x = (tid < 8) ? red[tid] : 0.0f;
        #pragma unroll
        for (int o = 4; o; o >>= 1) x += __shfl_xor_sync(0xffffffffu, x, o);
        if (tid == 0) red[0] = x;
    }
    __syncthreads();
    float r = red[0];
    __syncthreads();
    return r;
}

// ---------------- Weight prep (fused): fp32 -> bf16 hi/lo, [h][n][k] ----------
__global__ void k_prepW(const float* __restrict__ W1, const float* __restrict__ W2) {
    int gid = blockIdx.x * 256 + threadIdx.x;
    if (gid < 8 * 256 * 384) {                 // W_hid (8,256,384)
        int n = gid % 384;
        int hk = gid / 384;
        int k = hk & 255;
        int h = hk >> 8;
        float v = W1[gid];
        __nv_bfloat16 hh = __float2bfloat16_rn(v);
        __nv_bfloat16 ll = __float2bfloat16_rn(v - __bfloat162float(hh));
        int o = (h * 384 + n) * 256 + k;
        g_Wh_hi[o] = hh;
        g_Wh_lo[o] = ll;
    } else {                                   // W_og (8,256,128)
        int g2 = gid - 8 * 256 * 384;
        int n = g2 & 127;
        int k = (g2 >> 7) & 255;
        int h = g2 >> 15;
        float v = W2[g2];
        __nv_bfloat16 hh = __float2bfloat16_rn(v);
        __nv_bfloat16 ll = __float2bfloat16_rn(v - __bfloat162float(hh));
        int o = (h * 128 + n) * 256 + k;
        g_Wo_hi[o] = hh;
        g_Wo_lo[o] = ll;
    }
}

// ---------------- K1: per-chunk totals of hi (for cumsum offsets) -------------
__global__ __launch_bounds__(256) void k_ctot(const float* __restrict__ hi) {
    int b = blockIdx.x >> 7, chunk = blockIdx.x & 127;
    int hd = threadIdx.x * 4;
    long base = ((long)(b * SSEQ + chunk * CHS)) * HD + hd;
    float4 run = make_float4(0.f, 0.f, 0.f, 0.f);
    #pragma unroll
    for (int i0 = 0; i0 < CHS; i0 += 4) {
        float4 v0 = *(const float4*)(hi + base + (long)(i0 + 0) * HD);
        float4 v1 = *(const float4*)(hi + base + (long)(i0 + 1) * HD);
        float4 v2 = *(const float4*)(hi + base + (long)(i0 + 2) * HD);
        float4 v3 = *(const float4*)(hi + base + (long)(i0 + 3) * HD);
        run.x += v0.x + v1.x + v2.x + v3.x;
        run.y += v0.y + v1.y + v2.y + v3.y;
        run.z += v0.z + v1.z + v2.z + v3.z;
        run.w += v0.w + v1.w + v2.w + v3.w;
    }
    *(float4*)(g_ctot + (chunk * BB + b) * HD + hd) = run;
}

// ---------------- K2: scan chunk totals -> exclusive offsets ------------------
__global__ __launch_bounds__(256) void k_scanoff() {
    int gid = blockIdx.x * 256 + threadIdx.x;   // 0..1023
    int b = gid >> 8;
    int hd = (gid & 255) * 4;
    float4 run = make_float4(0.f, 0.f, 0.f, 0.f);
    #pragma unroll 8
    for (int c = 0; c < NCHS; c++) {
        float4 t = *(const float4*)(g_ctot + (c * BB + b) * HD + hd);
        *(float4*)(g_coff + (c * BB + b) * HD + hd) = run;
        run.x += t.x; run.y += t.y; run.z += t.z; run.w += t.w;
    }
}

// ---------------- K3: csum-LN stats (mu, rs) per token, reduce-only -----------
// CTA = (b, chunk of 32 tokens); 256 thr x 4 lanes hold running exclusive csum.
__global__ __launch_bounds__(256) void k_stats1(const float* __restrict__ hi) {
    __shared__ float red[32];
    int b = blockIdx.x >> 7, chunk = blockIdx.x & 127;
    int hd = threadIdx.x * 4;
    long base = ((long)(b * SSEQ + chunk * CHS)) * HD + hd;
    float4 run = *(const float4*)(g_coff + (chunk * BB + b) * HD + hd);
    for (int i = 0; i < CHS; i++) {
        float4 v = *(const float4*)(hi + base + (long)i * HD);
        float s = run.x + run.y + run.z + run.w;
        s = blockSum256(s, red);
        float mu = s * (1.0f / 1024.0f);
        float dx = run.x - mu, dy = run.y - mu, dz = run.z - mu, dw = run.w - mu;
        float q = dx * dx + dy * dy + dz * dz + dw * dw;
        q = blockSum256(q, red);
        if (threadIdx.x == 0) {
            float rs = rsqrtf(q * (1.0f / 1024.0f) + 1e-6f);
            g_stat[b * SSEQ + chunk * CHS + i] = make_float2(mu, rs);
        }
        run.x += v.x; run.y += v.y; run.z += v.z; run.w += v.w;
    }
}

// ---------------- GEMM common geometry ----------------------------------------
// CTA tile 64(M) x 128(N); A (full K=256) SMEM-resident hi/lo, looped over
// nTiles N-tiles. 2 CTAs/SM (104.4 KB SMEM). 8 warps 2(m) x 4(n).
// A stride 264 elems (528 B), B stride 72 elems (144 B) -> LDSM conflict-free.
#define GA_BYTES (64 * 264 * 2)          // 33792 per A tile
#define GB_BYTES (128 * 72 * 2)          // 18432 per B tile
#define SM_AHI  0
#define SM_ALO  (GA_BYTES)
#define SM_BHI  (2 * GA_BYTES)
#define SM_BLO  (2 * GA_BYTES + GB_BYTES)
#define SM_GEMM (2 * GA_BYTES + 2 * GB_BYTES)  // 104448

// MMA mainloop + epilogue shared by both GEMMs (A already in SMEM)
__device__ __forceinline__ void gemm_core(
    char* sm, uint32_t sb, int tid,
    const __nv_bfloat16* __restrict__ Whi, const __nv_bfloat16* __restrict__ Wlo,
    const float* __restrict__ bias, float* __restrict__ out,
    int Nw, int nTiles, int head, int tok0)
{
    int wid = tid >> 5, lid = tid & 31;
    int warp_m = wid >> 2, warp_n = wid & 3;
    int sub = lid >> 3, rin = lid & 7;

    for (int nt = 0; nt < nTiles; nt++) {
        int n0 = nt * 128;
        float acc[2][4][4];
        #pragma unroll
        for (int i = 0; i < 2; i++)
            #pragma unroll
            for (int j = 0; j < 4; j++)
                #pragma unroll
                for (int e = 0; e < 4; e++) acc[i][j][e] = 0.0f;

        for (int c = 0; c < 4; c++) {
            #pragma unroll
            for (int g = tid; g < 1024; g += 256) {
                int n = g >> 3, q = g & 7;
                long gb = (long)(head * Nw + n0 + n) * 256 + c * 64 + q * 8;
                uint4 vh = *(const uint4*)(Whi + gb);
                uint4 vl = *(const uint4*)(Wlo + gb);
                int off = n * 144 + q * 16;
                *(uint4*)(sm + SM_BHI + off) = vh;
                *(uint4*)(sm + SM_BLO + off) = vl;
            }
            __syncthreads();

            #pragma unroll
            for (int s = 0; s < 4; s++) {
                uint32_t Bh[4][2], Bl[4][2];
                #pragma unroll
                for (int p = 0; p < 2; p++) {
                    int brow = warp_n * 32 + p * 16 + rin + ((sub >> 1) << 3);
                    int bk = s * 16 + ((sub & 1) << 3);
                    uint32_t addr = sb + SM_BHI + brow * 144 + bk * 2;
                    uint32_t t4[4];
                    ldsm4(t4, addr);
                    Bh[2 * p][0] = t4[0]; Bh[2 * p][1] = t4[1];
                    Bh[2 * p + 1][0] = t4[2]; Bh[2 * p + 1][1] = t4[3];
                    ldsm4(t4, addr + (SM_BLO - SM_BHI));
                    Bl[2 * p][0] = t4[0]; Bl[2 * p][1] = t4[1];
                    Bl[2 * p + 1][0] = t4[2]; Bl[2 * p + 1][1] = t4[3];
                }
                #pragma unroll
                for (int mi = 0; mi < 2; mi++) {
                    int arow = warp_m * 32 + mi * 16 + rin + ((sub & 1) << 3);
                    int ak = c * 64 + s * 16 + ((sub >> 1) << 3);
                    uint32_t addr = sb + SM_AHI + arow * 528 + ak * 2;
                    uint32_t Ah[4], Al[4];
                    ldsm4(Ah, addr);
                    ldsm4(Al, addr + (SM_ALO - SM_AHI));
                    #pragma unroll
                    for (int ni = 0; ni < 4; ni++) {
                        mma16816(acc[mi][ni], Ah, Bh[ni]);
                        mma16816(acc[mi][ni], Ah, Bl[ni]);
                        mma16816(acc[mi][ni], Al, Bh[ni]);
                    }
                }
            }
            __syncthreads();
        }

        int g4 = lid >> 2, tg = lid & 3;
        #pragma unroll
        for (int mi = 0; mi < 2; mi++) {
            int r0 = tok0 + warp_m * 32 + mi * 16 + g4;
            #pragma unroll
            for (int ni = 0; ni < 4; ni++) {
                int ncol = n0 + warp_n * 32 + ni * 8 + tg * 2;
                float b0 = bias[head * Nw + ncol];
                float b1 = bias[head * Nw + ncol + 1];
                float2 o0 = make_float2(acc[mi][ni][0] + b0, acc[mi][ni][1] + b1);
                float2 o1 = make_float2(acc[mi][ni][2] + b0, acc[mi][ni][3] + b1);
                *(float2*)(out + ((long)r0 * 8 + head) * Nw + ncol) = o0;
                *(float2*)(out + ((long)(r0 + 8) * 8 + head) * Nw + ncol) = o1;
            }
        }
    }
}

// ---------------- K4: GEMM1 with inline exclusive-cumsum + csum-LN on A2 ------
__global__ __launch_bounds__(256, 2) void k_gemm1(
    const float* __restrict__ hi,
    const float* __restrict__ gcs, const float* __restrict__ bcs,
    const __nv_bfloat16* __restrict__ Whi, const __nv_bfloat16* __restrict__ Wlo,
    const float* __restrict__ bias, float* __restrict__ out)
{
    extern __shared__ char sm[];
    uint32_t sb = s2u(sm);
    int tid = threadIdx.x;
    int mtile = blockIdx.x, head = blockIdx.y;
    int tok0 = mtile * 64;

    // ---- A-fill: thread = (lane d, half), serial 32 tokens -------------------
    {
        int half = tid >> 7;            // 0..1 (token sub-chunk of 32)
        int d = tid & 127;
        int b = tok0 >> 12;
        int s0 = tok0 & (SSEQ - 1);
        int chunk = (s0 >> 5) + half;   // 32-token chunk index within b
        int hd = head * 128 + d;
        float run = g_coff[(chunk * BB + b) * HD + hd];
        float gc = gcs[hd], bc = bcs[hd];
        int r0 = half * 32;
        #pragma unroll 4
        for (int rr = 0; rr < 32; rr++) {
            int row = r0 + rr;
            int tok = tok0 + row;
            float v = hi[((long)tok * 8 + head) * 128 + d];
            float2 st = g_stat[tok];
            float a2 = (run - st.x) * st.y * gc + bc;   // exclusive csum, LN'd
            run += v;
            __nv_bfloat16 h1 = __float2bfloat16_rn(v);
            __nv_bfloat16 l1 = __float2bfloat16_rn(v - __bfloat162float(h1));
            __nv_bfloat16 h2 = __float2bfloat16_rn(a2);
            __nv_bfloat16 l2 = __float2bfloat16_rn(a2 - __bfloat162float(h2));
            int off = row * 528;
            *(__nv_bfloat16*)(sm + SM_AHI + off + d * 2) = h1;
            *(__nv_bfloat16*)(sm + SM_ALO + off + d * 2) = l1;
            *(__nv_bfloat16*)(sm + SM_AHI + off + (128 + d) * 2) = h2;
            *(__nv_bfloat16*)(sm + SM_ALO + off + (128 + d) * 2) = l2;
        }
    }
    __syncthreads();
    gemm_core(sm, sb, tid, Whi, Wlo, bias, out, 384, 3, head, tok0);
}

// ---------------- K7: GEMM2 (A2 = cell array) ---------------------------------
__global__ __launch_bounds__(256, 2) void k_gemm2(
    const float* __restrict__ A1, const float* __restrict__ A2,
    const __nv_bfloat16* __restrict__ Whi, const __nv_bfloat16* __restrict__ Wlo,
    const float* __restrict__ bias, float* __restrict__ out)
{
    extern __shared__ char sm[];
    uint32_t sb = s2u(sm);
    int tid = threadIdx.x;
    int mtile = blockIdx.x, head = blockIdx.y;
    int tok0 = mtile * 64;

    #pragma unroll
    for (int g = tid; g < 2048; g += 256) {     // 64 rows x 32 groups of 8
        int r = g >> 5, q = g & 31;
        const float* p = (q < 16)
            ? A1 + ((long)(tok0 + r) * 8 + head) * 128 + q * 8
            : A2 + ((long)(tok0 + r) * 8 + head) * 128 + (q - 16) * 8;
        float4 u0 = *(const float4*)p;
        float4 u1 = *(const float4*)(p + 4);
        float v[8] = {u0.x, u0.y, u0.z, u0.w, u1.x, u1.y, u1.z, u1.w};
        union { __nv_bfloat16 h[8]; uint4 u; } H, L;
        #pragma unroll
        for (int j = 0; j < 8; j++) {
            __nv_bfloat16 hh = __float2bfloat16_rn(v[j]);
            H.h[j] = hh;
            L.h[j] = __float2bfloat16_rn(v[j] - __bfloat162float(hh));
        }
        int off = r * 528 + q * 16;
        *(uint4*)(sm + SM_AHI + off) = H.u;
        *(uint4*)(sm + SM_ALO + off) = L.u;
    }
    __syncthreads();
    gemm_core(sm, sb, tid, Whi, Wlo, bias, out, 128, 1, head, tok0);
}

// ---------------- K5: LN over (H,3,DO)=3072 per token + gates -----------------
__global__ __launch_bounds__(256) void k_ln_gates(const float* __restrict__ gh,
                                                  const float* __restrict__ bh) {
    __shared__ float red[32];
    __shared__ float sm[3072];
    int t = blockIdx.x;
    int tid = threadIdx.x;
    float v[12];
    #pragma unroll
    for (int j = 0; j < 12; j++) v[j] = g_h3[(long)t * 3072 + tid + j * 256];
    float s1 = 0.0f;
    #pragma unroll
    for (int j = 0; j < 12; j++) s1 += v[j];
    s1 = blockSum256(s1, red);
    float mu = s1 * (1.0f / 3072.0f);
    float q = 0.0f;
    #pragma unroll
    for (int j = 0; j < 12; j++) { float d = v[j] - mu; q += d * d; }
    q = blockSum256(q, red);
    float rs = rsqrtf(q * (1.0f / 3072.0f) + 1e-6f);
    #pragma unroll
    for (int j = 0; j < 12; j++) {
        int e = tid + j * 256;
        sm[e] = (v[j] - mu) * rs * gh[e] + bh[e];
    }
    __syncthreads();
    #pragma unroll
    for (int j = 0; j < 4; j++) {
        int idx = tid + j * 256;          // n*128 + d
        int n = idx >> 7;
        int d = idx & 127;
        float ig = sm[n * 384 + d];
        float fg = sm[n * 384 + 128 + d];
        float hv = sm[n * 384 + 256 + d];
        g_fg[(long)t * HD + idx]  = sigmoidf_(fg);
        g_igh[(long)t * HD + idx] = sigmoidf_(ig) * fmaxf(hv, 0.0f);
    }
}

// ---------------- K6a/b/c: chunked linear-recurrence scan (float4, MLP-4) -----
__global__ __launch_bounds__(256) void k_scan_agg() {
    int b = blockIdx.x >> 7, chunk = blockIdx.x & 127;
    int hd = threadIdx.x * 4;
    long base = ((long)(b * SSEQ + chunk * CHS)) * HD + hd;
    float4 F = make_float4(1.f, 1.f, 1.f, 1.f);
    float4 I = make_float4(0.f, 0.f, 0.f, 0.f);
    #pragma unroll
    for (int i0 = 0; i0 < CHS; i0 += 4) {
        float4 f[4], g[4];
        #pragma unroll
        for (int u = 0; u < 4; u++) {
            f[u] = *(const float4*)(g_fg + base + (long)(i0 + u) * HD);
            g[u] = *(const float4*)(g_igh + base + (long)(i0 + u) * HD);
        }
        #pragma unroll
        for (int u = 0; u < 4; u++) {
            I.x = fmaf(f[u].x, I.x, g[u].x); I.y = fmaf(f[u].y, I.y, g[u].y);
            I.z = fmaf(f[u].z, I.z, g[u].z); I.w = fmaf(f[u].w, I.w, g[u].w);
            F.x *= f[u].x; F.y *= f[u].y; F.z *= f[u].z; F.w *= f[u].w;
        }
    }
    *(float4*)(g_aggF + (chunk * BB + b) * HD + hd) = F;
    *(float4*)(g_aggI + (chunk * BB + b) * HD + hd) = I;
}
__global__ __launch_bounds__(256) void k_scan_carry(const float* __restrict__ init_cx) {
    int gid = blockIdx.x * 256 + threadIdx.x;   // 0..1023
    int b = gid >> 8;
    int hd = (gid & 255) * 4;
    float4 c = *(const float4*)(init_cx + hd);
    #pragma unroll 8
    for (int chunk = 0; chunk < NCHS; chunk++) {
        int o = (chunk * BB + b) * HD + hd;
        *(float4*)(g_carry + o) = c;
        float4 F = *(const float4*)(g_aggF + o);
        float4 I = *(const float4*)(g_aggI + o);
        c.x = fmaf(F.x, c.x, I.x); c.y = fmaf(F.y, c.y, I.y);
        c.z = fmaf(F.z, c.z, I.z); c.w = fmaf(F.w, c.w, I.w);
    }
}
__global__ __launch_bounds__(256) void k_scan_apply() {
    int b = blockIdx.x >> 7, chunk = blockIdx.x & 127;
    int hd = threadIdx.x * 4;
    long base = ((long)(b * SSEQ + chunk * CHS)) * HD + hd;
    float4 c = *(const float4*)(g_carry + (chunk * BB + b) * HD + hd);
    #pragma unroll
    for (int i0 = 0; i0 < CHS; i0 += 4) {
        float4 f[4], g[4];
        #pragma unroll
        for (int u = 0; u < 4; u++) {
            f[u] = *(const float4*)(g_fg + base + (long)(i0 + u) * HD);
            g[u] = *(const float4*)(g_igh + base + (long)(i0 + u) * HD);
        }
        #pragma unroll
        for (int u = 0; u < 4; u++) {
            c.x = fmaf(f[u].x, c.x, g[u].x); c.y = fmaf(f[u].y, c.y, g[u].y);
            c.z = fmaf(f[u].z, c.z, g[u].z); c.w = fmaf(f[u].w, c.w, g[u].w);
            *(float4*)(g_cell + base + (long)(i0 + u) * HD) = c;
        }
    }
}

// ---------------- K8: final LN over (H,DO)=1024 + sigmoid * cell --------------
__global__ __launch_bounds__(256) void k_final(const float* __restrict__ gog,
                                               const float* __restrict__ bog,
                                               float* __restrict__ out) {
    __shared__ float red[32];
    int t = blockIdx.x;
    int tid = threadIdx.x;
    float v[4];
    #pragma unroll
    for (int j = 0; j < 4; j++) v[j] = g_h3[(long)t * HD + tid + j * 256];
    float s1 = v[0] + v[1] + v[2] + v[3];
    s1 = blockSum256(s1, red);
    float mu = s1 * (1.0f / 1024.0f);
    float q = 0.0f;
    #pragma unroll
    for (int j = 0; j < 4; j++) { float d = v[j] - mu; q += d * d; }
    q = blockSum256(q, red);
    float rs = rsqrtf(q * (1.0f / 1024.0f) + 1e-6f);
    #pragma unroll
    for (int j = 0; j < 4; j++) {
        int idx = tid + j * 256;
        float og = (v[j] - mu) * rs * gog[idx] + bog[idx];
        out[(long)t * HD + idx] = sigmoidf_(og) * g_cell[(long)t * HD + idx];
    }
}

// ------------------------------------------------------------------------------
extern "C" void kernel_launch(void* const* d_in, const int* in_sizes, int n_in,
                              void* d_out, int out_size) {
    const float* hi        = (const float*)d_in[0];
    const float* W_hid     = (const float*)d_in[1];
    const float* b_hid     = (const float*)d_in[2];
    const float* gcsum     = (const float*)d_in[3];
    const float* bcsum     = (const float*)d_in[4];
    const float* g_hid     = (const float*)d_in[5];
    const float* beta_hid  = (const float*)d_in[6];
    const float* W_og      = (const float*)d_in[7];
    const float* b_og      = (const float*)d_in[8];
    const float* g_og      = (const float*)d_in[9];
    const float* beta_og   = (const float*)d_in[10];
    const float* init_cx   = (const float*)d_in[11];
    float* out = (float*)d_out;

    cudaFuncSetAttribute(k_gemm1, cudaFuncAttributeMaxDynamicSharedMemorySize, SM_GEMM);
    cudaFuncSetAttribute(k_gemm2, cudaFuncAttributeMaxDynamicSharedMemorySize, SM_GEMM);

    float* cell_p; cudaGetSymbolAddress((void**)&cell_p, g_cell);
    float* h3_p;   cudaGetSymbolAddress((void**)&h3_p,   g_h3);
    __nv_bfloat16 *wh_hi, *wh_lo, *wo_hi, *wo_lo;
    cudaGetSymbolAddress((void**)&wh_hi, g_Wh_hi);
    cudaGetSymbolAddress((void**)&wh_lo, g_Wh_lo);
    cudaGetSymbolAddress((void**)&wo_hi, g_Wo_hi);
    cudaGetSymbolAddress((void**)&wo_lo, g_Wo_lo);

    k_prepW<<<4096, 256>>>(W_hid, W_og);                 // 0
    k_ctot<<<512, 256>>>(hi);                            // 1
    k_scanoff<<<4, 256>>>();                             // 2
    k_stats1<<<512, 256>>>(hi);                          // 3  <- ncu slot
    k_gemm1<<<dim3(256, 8), 256, SM_GEMM>>>(hi, gcsum, bcsum, wh_hi, wh_lo,
                                            b_hid, h3_p);
    k_ln_gates<<<NTOK, 256>>>(g_hid, beta_hid);
    k_scan_agg<<<512, 256>>>();
    k_scan_carry<<<4, 256>>>(init_cx);
    k_scan_apply<<<512, 256>>>();
    k_gemm2<<<dim3(256, 8), 256, SM_GEMM>>>(hi, cell_p, wo_hi, wo_lo,
                                            b_og, h3_p);
    k_final<<<NTOK, 256>>>(g_og, beta_og, out);
}

// round 14
// speedup vs baseline: 2.1599x; 1.0830x over previous
#include <cuda_runtime.h>
#include <cuda_bf16.h>
#include <cuda_fp16.h>
#include <cstdint>
#include <math.h>

// Problem constants
#define BB 4
#define SSEQ 4096
#define HH 8
#define DI 128
#define DOUT 128
#define HD 1024            // HH*DI
#define NTOK (BB*SSEQ)     // 16384
#define CHS 32             // scan / cumsum chunk length
#define NCHS 128           // SSEQ / CHS

// ---------------- scratch (static device globals; no allocations) -------------
__device__ __half  g_h3h[(long)NTOK * HH * 384];  // h3 raw (fp16); reused as og
__device__ __half2 g_gates[(long)NTOK * HD];      // (fg, igh) packed fp16
__device__ float g_cell[(long)NTOK * HD];    // scan output (fp32)
__device__ float g_ctot[NCHS * BB * HD];     // [chunk][b][hd] cumsum chunk totals
__device__ float g_coff[NCHS * BB * HD];     // exclusive chunk offsets
__device__ float g_aggF[NCHS * BB * HD];
__device__ float g_aggI[NCHS * BB * HD];
__device__ float g_carry[NCHS * BB * HD];
__device__ float2 g_stat[NTOK];              // (mu, rs) of csum-LN per token

// bf16 hi/lo split weights, K-major ([head][n][k])
__device__ __nv_bfloat16 g_Wh_hi[8 * 384 * 256];
__device__ __nv_bfloat16 g_Wh_lo[8 * 384 * 256];
__device__ __nv_bfloat16 g_Wo_hi[8 * 128 * 256];
__device__ __nv_bfloat16 g_Wo_lo[8 * 128 * 256];

// fast sigmoid via HW tanh: sigmoid(x) = 0.5*tanh(x/2)+0.5
__device__ __forceinline__ float sigmoidf_(float x) {
    float t;
    asm("tanh.approx.f32 %0, %1;" : "=f"(t) : "f"(0.5f * x));
    return fmaf(0.5f, t, 0.5f);
}

// ======================= mma.sync / ldmatrix helpers ==========================
__device__ __forceinline__ uint32_t s2u(const void* p) {
    uint32_t a;
    asm("{ .reg .u64 t; cvta.to.shared.u64 t, %1; cvt.u32.u64 %0, t; }" : "=r"(a) : "l"(p));
    return a;
}
__device__ __forceinline__ void ldsm4(uint32_t r[4], uint32_t addr) {
    asm volatile("ldmatrix.sync.aligned.m8n8.x4.shared.b16 {%0,%1,%2,%3}, [%4];"
                 : "=r"(r[0]), "=r"(r[1]), "=r"(r[2]), "=r"(r[3]) : "r"(addr));
}
__device__ __forceinline__ void mma16816(float* c, const uint32_t* a, const uint32_t* b) {
    asm volatile(
        "mma.sync.aligned.m16n8k16.row.col.f32.bf16.bf16.f32 "
        "{%0,%1,%2,%3}, {%4,%5,%6,%7}, {%8,%9}, {%0,%1,%2,%3};"
        : "+f"(c[0]), "+f"(c[1]), "+f"(c[2]), "+f"(c[3])
        : "r"(a[0]), "r"(a[1]), "r"(a[2]), "r"(a[3]), "r"(b[0]), "r"(b[1]));
}

// block-wide sum reduction (blockDim.x == 256), result broadcast
__device__ __forceinline__ float blockSum256(float v, float* red) {
    int tid = threadIdx.x;
    #pragma unroll
    for (int o = 16; o; o >>= 1) v += __shfl_xor_sync(0xffffffffu, v, o);
    if ((tid & 31) == 0) red[tid >> 5] = v;
    __syncthreads();
    if (tid < 32) {
        float x = (tid < 8) ? red[tid] : 0.0f;
        #pragma unroll
        for (int o = 4; o; o >>= 1) x += __shfl_xor_sync(0xffffffffu, x, o);
        if (tid == 0) red[0] = x;
    }
    __syncthreads();
    float r = red[0];
    __syncthreads();
    return r;
}

// ---------------- Weight prep (fused): fp32 -> bf16 hi/lo, [h][n][k] ----------
__global__ void k_prepW(const float* __restrict__ W1, const float* __restrict__ W2) {
    int gid = blockIdx.x * 256 + threadIdx.x;
    if (gid < 8 * 256 * 384) {                 // W_hid (8,256,384)
        int n = gid % 384;
        int hk = gid / 384;
        int k = hk & 255;
        int h = hk >> 8;
        float v = W1[gid];
        __nv_bfloat16 hh = __float2bfloat16_rn(v);
        __nv_bfloat16 ll = __float2bfloat16_rn(v - __bfloat162float(hh));
        int o = (h * 384 + n) * 256 + k;
        g_Wh_hi[o] = hh;
        g_Wh_lo[o] = ll;
    } else {                                   // W_og (8,256,128)
        int g2 = gid - 8 * 256 * 384;
        int n = g2 & 127;
        int k = (g2 >> 7) & 255;
        int h = g2 >> 15;
        float v = W2[g2];
        __nv_bfloat16 hh = __float2bfloat16_rn(v);
        __nv_bfloat16 ll = __float2bfloat16_rn(v - __bfloat162float(hh));
        int o = (h * 128 + n) * 256 + k;
        g_Wo_hi[o] = hh;
        g_Wo_lo[o] = ll;
    }
}

// ---------------- K1: per-chunk totals of hi (for cumsum offsets) -------------
__global__ __launch_bounds__(256) void k_ctot(const float* __restrict__ hi) {
    int b = blockIdx.x >> 7, chunk = blockIdx.x & 127;
    int hd = threadIdx.x * 4;
    long base = ((long)(b * SSEQ + chunk * CHS)) * HD + hd;
    float4 run = make_float4(0.f, 0.f, 0.f, 0.f);
    #pragma unroll
    for (int i0 = 0; i0 < CHS; i0 += 4) {
        float4 v0 = *(const float4*)(hi + base + (long)(i0 + 0) * HD);
        float4 v1 = *(const float4*)(hi + base + (long)(i0 + 1) * HD);
        float4 v2 = *(const float4*)(hi + base + (long)(i0 + 2) * HD);
        float4 v3 = *(const float4*)(hi + base + (long)(i0 + 3) * HD);
        run.x += v0.x + v1.x + v2.x + v3.x;
        run.y += v0.y + v1.y + v2.y + v3.y;
        run.z += v0.z + v1.z + v2.z + v3.z;
        run.w += v0.w + v1.w + v2.w + v3.w;
    }
    *(float4*)(g_ctot + (chunk * BB + b) * HD + hd) = run;
}

// ---------------- K2: scan chunk totals -> exclusive offsets ------------------
__global__ __launch_bounds__(256) void k_scanoff() {
    int gid = blockIdx.x * 256 + threadIdx.x;   // 0..1023
    int b = gid >> 8;
    int hd = (gid & 255) * 4;
    float4 run = make_float4(0.f, 0.f, 0.f, 0.f);
    #pragma unroll 8
    for (int c = 0; c < NCHS; c++) {
        float4 t = *(const float4*)(g_ctot + (c * BB + b) * HD + hd);
        *(float4*)(g_coff + (c * BB + b) * HD + hd) = run;
        run.x += t.x; run.y += t.y; run.z += t.z; run.w += t.w;
    }
}

// ---------------- K3: csum-LN stats (mu, rs) per token, reduce-only -----------
__global__ __launch_bounds__(256) void k_stats1(const float* __restrict__ hi) {
    __shared__ float red[32];
    int b = blockIdx.x >> 7, chunk = blockIdx.x & 127;
    int hd = threadIdx.x * 4;
    long base = ((long)(b * SSEQ + chunk * CHS)) * HD + hd;
    float4 run = *(const float4*)(g_coff + (chunk * BB + b) * HD + hd);
    for (int i = 0; i < CHS; i++) {
        float4 v = *(const float4*)(hi + base + (long)i * HD);
        float s = run.x + run.y + run.z + run.w;
        s = blockSum256(s, red);
        float mu = s * (1.0f / 1024.0f);
        float dx = run.x - mu, dy = run.y - mu, dz = run.z - mu, dw = run.w - mu;
        float q = dx * dx + dy * dy + dz * dz + dw * dw;
        q = blockSum256(q, red);
        if (threadIdx.x == 0) {
            float rs = rsqrtf(q * (1.0f / 1024.0f) + 1e-6f);
            g_stat[b * SSEQ + chunk * CHS + i] = make_float2(mu, rs);
        }
        run.x += v.x; run.y += v.y; run.z += v.z; run.w += v.w;
    }
}

// ---------------- GEMM common geometry ----------------------------------------
#define GA_BYTES (64 * 264 * 2)          // 33792 per A tile
#define GB_BYTES (128 * 72 * 2)          // 18432 per B tile
#define SM_AHI  0
#define SM_ALO  (GA_BYTES)
#define SM_BHI  (2 * GA_BYTES)
#define SM_BLO  (2 * GA_BYTES + GB_BYTES)
#define SM_GEMM (2 * GA_BYTES + 2 * GB_BYTES)  // 104448

// MMA mainloop + epilogue (fp16 output) shared by both GEMMs (A already in SMEM)
__device__ __forceinline__ void gemm_core(
    char* sm, uint32_t sb, int tid,
    const __nv_bfloat16* __restrict__ Whi, const __nv_bfloat16* __restrict__ Wlo,
    const float* __restrict__ bias, __half* __restrict__ out,
    int Nw, int nTiles, int head, int tok0)
{
    int wid = tid >> 5, lid = tid & 31;
    int warp_m = wid >> 2, warp_n = wid & 3;
    int sub = lid >> 3, rin = lid & 7;

    for (int nt = 0; nt < nTiles; nt++) {
        int n0 = nt * 128;
        float acc[2][4][4];
        #pragma unroll
        for (int i = 0; i < 2; i++)
            #pragma unroll
            for (int j = 0; j < 4; j++)
                #pragma unroll
                for (int e = 0; e < 4; e++) acc[i][j][e] = 0.0f;

        for (int c = 0; c < 4; c++) {
            #pragma unroll
            for (int g = tid; g < 1024; g += 256) {
                int n = g >> 3, q = g & 7;
                long gb = (long)(head * Nw + n0 + n) * 256 + c * 64 + q * 8;
                uint4 vh = *(const uint4*)(Whi + gb);
                uint4 vl = *(const uint4*)(Wlo + gb);
                int off = n * 144 + q * 16;
                *(uint4*)(sm + SM_BHI + off) = vh;
                *(uint4*)(sm + SM_BLO + off) = vl;
            }
            __syncthreads();

            #pragma unroll
            for (int s = 0; s < 4; s++) {
                uint32_t Bh[4][2], Bl[4][2];
                #pragma unroll
                for (int p = 0; p < 2; p++) {
                    int brow = warp_n * 32 + p * 16 + rin + ((sub >> 1) << 3);
                    int bk = s * 16 + ((sub & 1) << 3);
                    uint32_t addr = sb + SM_BHI + brow * 144 + bk * 2;
                    uint32_t t4[4];
                    ldsm4(t4, addr);
                    Bh[2 * p][0] = t4[0]; Bh[2 * p][1] = t4[1];
                    Bh[2 * p + 1][0] = t4[2]; Bh[2 * p + 1][1] = t4[3];
                    ldsm4(t4, addr + (SM_BLO - SM_BHI));
                    Bl[2 * p][0] = t4[0]; Bl[2 * p][1] = t4[1];
                    Bl[2 * p + 1][0] = t4[2]; Bl[2 * p + 1][1] = t4[3];
                }
                #pragma unroll
                for (int mi = 0; mi < 2; mi++) {
                    int arow = warp_m * 32 + mi * 16 + rin + ((sub & 1) << 3);
                    int ak = c * 64 + s * 16 + ((sub >> 1) << 3);
                    uint32_t addr = sb + SM_AHI + arow * 528 + ak * 2;
                    uint32_t Ah[4], Al[4];
                    ldsm4(Ah, addr);
                    ldsm4(Al, addr + (SM_ALO - SM_AHI));
                    #pragma unroll
                    for (int ni = 0; ni < 4; ni++) {
                        mma16816(acc[mi][ni], Ah, Bh[ni]);
                        mma16816(acc[mi][ni], Ah, Bl[ni]);
                        mma16816(acc[mi][ni], Al, Bh[ni]);
                    }
                }
            }
            __syncthreads();
        }

        int g4 = lid >> 2, tg = lid & 3;
        #pragma unroll
        for (int mi = 0; mi < 2; mi++) {
            int r0 = tok0 + warp_m * 32 + mi * 16 + g4;
            #pragma unroll
            for (int ni = 0; ni < 4; ni++) {
                int ncol = n0 + warp_n * 32 + ni * 8 + tg * 2;
                float b0 = bias[head * Nw + ncol];
                float b1 = bias[head * Nw + ncol + 1];
                __half2 o0 = __floats2half2_rn(acc[mi][ni][0] + b0, acc[mi][ni][1] + b1);
                __half2 o1 = __floats2half2_rn(acc[mi][ni][2] + b0, acc[mi][ni][3] + b1);
                *(__half2*)(out + ((long)r0 * 8 + head) * Nw + ncol) = o0;
                *(__half2*)(out + ((long)(r0 + 8) * 8 + head) * Nw + ncol) = o1;
            }
        }
    }
}

// ---------------- K4: GEMM1 with inline exclusive-cumsum + csum-LN on A2 ------
__global__ __launch_bounds__(256, 2) void k_gemm1(
    const float* __restrict__ hi,
    const float* __restrict__ gcs, const float* __restrict__ bcs,
    const __nv_bfloat16* __restrict__ Whi, const __nv_bfloat16* __restrict__ Wlo,
    const float* __restrict__ bias, __half* __restrict__ out)
{
    extern __shared__ char sm[];
    uint32_t sb = s2u(sm);
    int tid = threadIdx.x;
    int mtile = blockIdx.x, head = blockIdx.y;
    int tok0 = mtile * 64;

    // ---- A-fill: thread = (lane d, half), serial 32 tokens -------------------
    {
        int half_ = tid >> 7;           // 0..1 (token sub-chunk of 32)
        int d = tid & 127;
        int b = tok0 >> 12;
        int s0 = tok0 & (SSEQ - 1);
        int chunk = (s0 >> 5) + half_;
        int hd = head * 128 + d;
        float run = g_coff[(chunk * BB + b) * HD + hd];
        float gc = gcs[hd], bc = bcs[hd];
        int r0 = half_ * 32;
        #pragma unroll 4
        for (int rr = 0; rr < 32; rr++) {
            int row = r0 + rr;
            int tok = tok0 + row;
            float v = hi[((long)tok * 8 + head) * 128 + d];
            float2 st = g_stat[tok];
            float a2 = (run - st.x) * st.y * gc + bc;   // exclusive csum, LN'd
            run += v;
            __nv_bfloat16 h1 = __float2bfloat16_rn(v);
            __nv_bfloat16 l1 = __float2bfloat16_rn(v - __bfloat162float(h1));
            __nv_bfloat16 h2 = __float2bfloat16_rn(a2);
            __nv_bfloat16 l2 = __float2bfloat16_rn(a2 - __bfloat162float(h2));
            int off = row * 528;
            *(__nv_bfloat16*)(sm + SM_AHI + off + d * 2) = h1;
            *(__nv_bfloat16*)(sm + SM_ALO + off + d * 2) = l1;
            *(__nv_bfloat16*)(sm + SM_AHI + off + (128 + d) * 2) = h2;
            *(__nv_bfloat16*)(sm + SM_ALO + off + (128 + d) * 2) = l2;
        }
    }
    __syncthreads();
    gemm_core(sm, sb, tid, Whi, Wlo, bias, out, 384, 3, head, tok0);
}

// ---------------- K7: GEMM2 (A2 = cell array, fp32) ---------------------------
__global__ __launch_bounds__(256, 2) void k_gemm2(
    const float* __restrict__ A1, const float* __restrict__ A2,
    const __nv_bfloat16* __restrict__ Whi, const __nv_bfloat16* __restrict__ Wlo,
    const float* __restrict__ bias, __half* __restrict__ out)
{
    extern __shared__ char sm[];
    uint32_t sb = s2u(sm);
    int tid = threadIdx.x;
    int mtile = blockIdx.x, head = blockIdx.y;
    int tok0 = mtile * 64;

    #pragma unroll
    for (int g = tid; g < 2048; g += 256) {     // 64 rows x 32 groups of 8
        int r = g >> 5, q = g & 31;
        const float* p = (q < 16)
            ? A1 + ((long)(tok0 + r) * 8 + head) * 128 + q * 8
            : A2 + ((long)(tok0 + r) * 8 + head) * 128 + (q - 16) * 8;
        float4 u0 = *(const float4*)p;
        float4 u1 = *(const float4*)(p + 4);
        float v[8] = {u0.x, u0.y, u0.z, u0.w, u1.x, u1.y, u1.z, u1.w};
        union { __nv_bfloat16 h[8]; uint4 u; } H, L;
        #pragma unroll
        for (int j = 0; j < 8; j++) {
            __nv_bfloat16 hh = __float2bfloat16_rn(v[j]);
            H.h[j] = hh;
            L.h[j] = __float2bfloat16_rn(v[j] - __bfloat162float(hh));
        }
        int off = r * 528 + q * 16;
        *(uint4*)(sm + SM_AHI + off) = H.u;
        *(uint4*)(sm + SM_ALO + off) = L.u;
    }
    __syncthreads();
    gemm_core(sm, sb, tid, Whi, Wlo, bias, out, 128, 1, head, tok0);
}

// ---------------- K5: LN over (H,3,DO)=3072 per token + gates (fp16 I/O) ------
__global__ __launch_bounds__(256) void k_ln_gates(const float* __restrict__ gh,
                                                  const float* __restrict__ bh) {
    __shared__ float red[32];
    __shared__ float smv[3072];
    int t = blockIdx.x;
    int tid = threadIdx.x;
    const __half2* hp = (const __half2*)(g_h3h + (long)t * 3072);
    float2 v[6];
    #pragma unroll
    for (int j = 0; j < 6; j++) v[j] = __half22float2(hp[tid + j * 256]);
    float s1 = 0.0f;
    #pragma unroll
    for (int j = 0; j < 6; j++) s1 += v[j].x + v[j].y;
    s1 = blockSum256(s1, red);
    float mu = s1 * (1.0f / 3072.0f);
    float q = 0.0f;
    #pragma unroll
    for (int j = 0; j < 6; j++) {
        float dx = v[j].x - mu, dy = v[j].y - mu;
        q += dx * dx + dy * dy;
    }
    q = blockSum256(q, red);
    float rs = rsqrtf(q * (1.0f / 3072.0f) + 1e-6f);
    #pragma unroll
    for (int j = 0; j < 6; j++) {
        int e = (tid + j * 256) * 2;
        smv[e]     = (v[j].x - mu) * rs * gh[e] + bh[e];
        smv[e + 1] = (v[j].y - mu) * rs * gh[e + 1] + bh[e + 1];
    }
    __syncthreads();
    #pragma unroll
    for (int j = 0; j < 4; j++) {
        int idx = tid + j * 256;          // n*128 + d
        int n = idx >> 7;
        int d = idx & 127;
        float ig = smv[n * 384 + d];
        float fg = smv[n * 384 + 128 + d];
        float hv = smv[n * 384 + 256 + d];
        float f = sigmoidf_(fg);
        float i = sigmoidf_(ig) * fmaxf(hv, 0.0f);
        g_gates[(long)t * HD + idx] = __floats2half2_rn(f, i);
    }
}

// ---------------- K6a/b/c: chunked linear-recurrence scan ---------------------
__global__ __launch_bounds__(256) void k_scan_agg() {
    int b = blockIdx.x >> 7, chunk = blockIdx.x & 127;
    int hd = threadIdx.x * 4;
    long base = ((long)(b * SSEQ + chunk * CHS)) * HD + hd;
    float4 F = make_float4(1.f, 1.f, 1.f, 1.f);
    float4 I = make_float4(0.f, 0.f, 0.f, 0.f);
    #pragma unroll
    for (int i0 = 0; i0 < CHS; i0 += 4) {
        uint4 u[4];
        #pragma unroll
        for (int v = 0; v < 4; v++)
            u[v] = *(const uint4*)(g_gates + base + (long)(i0 + v) * HD);
        #pragma unroll
        for (int v = 0; v < 4; v++) {
            __half2* hp = (__half2*)&u[v];
            float2 p0 = __half22float2(hp[0]);
            float2 p1 = __half22float2(hp[1]);
            float2 p2 = __half22float2(hp[2]);
            float2 p3 = __half22float2(hp[3]);
            I.x = fmaf(p0.x, I.x, p0.y); F.x *= p0.x;
            I.y = fmaf(p1.x, I.y, p1.y); F.y *= p1.x;
            I.z = fmaf(p2.x, I.z, p2.y); F.z *= p2.x;
            I.w = fmaf(p3.x, I.w, p3.y); F.w *= p3.x;
        }
    }
    *(float4*)(g_aggF + (chunk * BB + b) * HD + hd) = F;
    *(float4*)(g_aggI + (chunk * BB + b) * HD + hd) = I;
}
__global__ __launch_bounds__(256) void k_scan_carry(const float* __restrict__ init_cx) {
    int gid = blockIdx.x * 256 + threadIdx.x;   // 0..1023
    int b = gid >> 8;
    int hd = (gid & 255) * 4;
    float4 c = *(const float4*)(init_cx + hd);
    #pragma unroll 8
    for (int chunk = 0; chunk < NCHS; chunk++) {
        int o = (chunk * BB + b) * HD + hd;
        *(float4*)(g_carry + o) = c;
        float4 F = *(const float4*)(g_aggF + o);
        float4 I = *(const float4*)(g_aggI + o);
        c.x = fmaf(F.x, c.x, I.x); c.y = fmaf(F.y, c.y, I.y);
        c.z = fmaf(F.z, c.z, I.z); c.w = fmaf(F.w, c.w, I.w);
    }
}
__global__ __launch_bounds__(256) void k_scan_apply() {
    int b = blockIdx.x >> 7, chunk = blockIdx.x & 127;
    int hd = threadIdx.x * 4;
    long base = ((long)(b * SSEQ + chunk * CHS)) * HD + hd;
    float4 c = *(const float4*)(g_carry + (chunk * BB + b) * HD + hd);
    #pragma unroll
    for (int i0 = 0; i0 < CHS; i0 += 4) {
        uint4 u[4];
        #pragma unroll
        for (int v = 0; v < 4; v++)
            u[v] = *(const uint4*)(g_gates + base + (long)(i0 + v) * HD);
        #pragma unroll
        for (int v = 0; v < 4; v++) {
            __half2* hp = (__half2*)&u[v];
            float2 p0 = __half22float2(hp[0]);
            float2 p1 = __half22float2(hp[1]);
            float2 p2 = __half22float2(hp[2]);
            float2 p3 = __half22float2(hp[3]);
            c.x = fmaf(p0.x, c.x, p0.y);
            c.y = fmaf(p1.x, c.y, p1.y);
            c.z = fmaf(p2.x, c.z, p2.y);
            c.w = fmaf(p3.x, c.w, p3.y);
            *(float4*)(g_cell + base + (long)(i0 + v) * HD) = c;
        }
    }
}

// ---------------- K8: final LN over (H,DO)=1024 + sigmoid * cell --------------
__global__ __launch_bounds__(256) void k_final(const float* __restrict__ gog,
                                               const float* __restrict__ bog,
                                               float* __restrict__ out) {
    __shared__ float red[32];
    int t = blockIdx.x;
    int tid = threadIdx.x;
    int e0 = tid * 4;
    float v[4];
    {
        uint2 u = *(const uint2*)(g_h3h + (long)t * HD + e0);
        __half2* hp = (__half2*)&u;
        float2 p0 = __half22float2(hp[0]);
        float2 p1 = __half22float2(hp[1]);
        v[0] = p0.x; v[1] = p0.y; v[2] = p1.x; v[3] = p1.y;
    }
    float s1 = v[0] + v[1] + v[2] + v[3];
    s1 = blockSum256(s1, red);
    float mu = s1 * (1.0f / 1024.0f);
    float q = 0.0f;
    #pragma unroll
    for (int j = 0; j < 4; j++) { float d = v[j] - mu; q += d * d; }
    q = blockSum256(q, red);
    float rs = rsqrtf(q * (1.0f / 1024.0f) + 1e-6f);
    float4 gg = *(const float4*)(gog + e0);
    float4 bb = *(const float4*)(bog + e0);
    float4 cc = *(const float4*)(g_cell + (long)t * HD + e0);
    float4 o;
    o.x = sigmoidf_((v[0] - mu) * rs * gg.x + bb.x) * cc.x;
    o.y = sigmoidf_((v[1] - mu) * rs * gg.y + bb.y) * cc.y;
    o.z = sigmoidf_((v[2] - mu) * rs * gg.z + bb.z) * cc.z;
    o.w = sigmoidf_((v[3] - mu) * rs * gg.w + bb.w) * cc.w;
    *(float4*)(out + (long)t * HD + e0) = o;
}

// ------------------------------------------------------------------------------
extern "C" void kernel_launch(void* const* d_in, const int* in_sizes, int n_in,
                              void* d_out, int out_size) {
    const float* hi        = (const float*)d_in[0];
    const float* W_hid     = (const float*)d_in[1];
    const float* b_hid     = (const float*)d_in[2];
    const float* gcsum     = (const float*)d_in[3];
    const float* bcsum     = (const float*)d_in[4];
    const float* g_hid     = (const float*)d_in[5];
    const float* beta_hid  = (const float*)d_in[6];
    const float* W_og      = (const float*)d_in[7];
    const float* b_og      = (const float*)d_in[8];
    const float* g_og      = (const float*)d_in[9];
    const float* beta_og   = (const float*)d_in[10];
    const float* init_cx   = (const float*)d_in[11];
    float* out = (float*)d_out;

    cudaFuncSetAttribute(k_gemm1, cudaFuncAttributeMaxDynamicSharedMemorySize, SM_GEMM);
    cudaFuncSetAttribute(k_gemm2, cudaFuncAttributeMaxDynamicSharedMemorySize, SM_GEMM);

    float* cell_p; cudaGetSymbolAddress((void**)&cell_p, g_cell);
    __half* h3_p;  cudaGetSymbolAddress((void**)&h3_p,   g_h3h);
    __nv_bfloat16 *wh_hi, *wh_lo, *wo_hi, *wo_lo;
    cudaGetSymbolAddress((void**)&wh_hi, g_Wh_hi);
    cudaGetSymbolAddress((void**)&wh_lo, g_Wh_lo);
    cudaGetSymbolAddress((void**)&wo_hi, g_Wo_hi);
    cudaGetSymbolAddress((void**)&wo_lo, g_Wo_lo);

    k_prepW<<<4096, 256>>>(W_hid, W_og);                 // 0
    k_ctot<<<512, 256>>>(hi);                            // 1
    k_scanoff<<<4, 256>>>();                             // 2
    k_stats1<<<512, 256>>>(hi);                          // 3  <- ncu slot
    k_gemm1<<<dim3(256, 8), 256, SM_GEMM>>>(hi, gcsum, bcsum, wh_hi, wh_lo,
                                            b_hid, h3_p);
    k_ln_gates<<<NTOK, 256>>>(g_hid, beta_hid);
    k_scan_agg<<<512, 256>>>();
    k_scan_carry<<<4, 256>>>(init_cx);
    k_scan_apply<<<512, 256>>>();
    k_gemm2<<<dim3(256, 8), 256, SM_GEMM>>>(hi, cell_p, wo_hi, wo_lo,
                                            b_og, h3_p);
    k_final<<<NTOK, 256>>>(g_og, beta_og, out);
}